// round 2
// baseline (speedup 1.0000x reference)
#include <cuda_runtime.h>
#include <math.h>

#define B_  2
#define S_  2048
#define E_  2048
#define H_  16
#define D_  128
#define E3_ 6144

// ---------------- scratch (static device globals; no runtime allocation) ----
__device__ float g_qkv[B_ * S_ * E3_];      // QKV GEMM output  [B,S,3E]
__device__ float g_q[B_ * H_ * S_ * D_];    // rotated+scaled Q [B,H,S,D]
__device__ float g_k[B_ * H_ * S_ * D_];    // rotated K        [B,H,S,D]
__device__ float g_v[B_ * H_ * S_ * D_];    // V                [B,H,S,D]
__device__ float g_ao[B_ * S_ * E_];        // attention output [B,S,E]

// ============================================================================
// SGEMM: C[M,N] = A[M,K] @ B[K,N], all row-major. 128x128 tile, 8x8 microtile,
// BK=16, 256 threads. A staged transposed in smem (pad to 132 for bank safety).
// ============================================================================
__global__ __launch_bounds__(256) void sgemm128(
    const float* __restrict__ A, const float* __restrict__ Bm,
    float* __restrict__ C, int M, int N, int K)
{
    __shared__ float As[16][132];   // As[k][m]
    __shared__ float Bs[16][128];   // Bs[k][n]

    const int tid = threadIdx.x;
    const int bm0 = blockIdx.y * 128;
    const int bn0 = blockIdx.x * 128;

    // load mappings
    const int rowA  = tid & 127;      // 0..127
    const int halfA = tid >> 7;       // 0..1  (8 floats each)
    const int rowB  = tid >> 4;       // 0..15
    const int c8    = tid & 15;       // 8 floats each

    const float* Ap = A + (size_t)(bm0 + rowA) * K + halfA * 8;
    const float* Bp = Bm + (size_t)rowB * N + bn0 + c8 * 8;

    // compute mapping
    const int tr = (tid >> 4) * 8;
    const int tc = (tid & 15) * 8;

    float acc[8][8];
#pragma unroll
    for (int i = 0; i < 8; ++i)
#pragma unroll
        for (int j = 0; j < 8; ++j) acc[i][j] = 0.f;

    float4 pa0, pa1, pb0, pb1;
    pa0 = *(const float4*)(Ap);
    pa1 = *(const float4*)(Ap + 4);
    pb0 = *(const float4*)(Bp);
    pb1 = *(const float4*)(Bp + 4);

    const int ntiles = K / 16;
    for (int t = 0; t < ntiles; ++t) {
        // stage prefetched tile into smem
        As[halfA * 8 + 0][rowA] = pa0.x;
        As[halfA * 8 + 1][rowA] = pa0.y;
        As[halfA * 8 + 2][rowA] = pa0.z;
        As[halfA * 8 + 3][rowA] = pa0.w;
        As[halfA * 8 + 4][rowA] = pa1.x;
        As[halfA * 8 + 5][rowA] = pa1.y;
        As[halfA * 8 + 6][rowA] = pa1.z;
        As[halfA * 8 + 7][rowA] = pa1.w;
        *(float4*)&Bs[rowB][c8 * 8]     = pb0;
        *(float4*)&Bs[rowB][c8 * 8 + 4] = pb1;
        __syncthreads();

        if (t + 1 < ntiles) {
            const float* Ap2 = Ap + (t + 1) * 16;
            const float* Bp2 = Bp + (size_t)(t + 1) * 16 * N;
            pa0 = *(const float4*)(Ap2);
            pa1 = *(const float4*)(Ap2 + 4);
            pb0 = *(const float4*)(Bp2);
            pb1 = *(const float4*)(Bp2 + 4);
        }

#pragma unroll
        for (int kk = 0; kk < 16; ++kk) {
            float a[8], b[8];
            *(float4*)(a)     = *(const float4*)&As[kk][tr];
            *(float4*)(a + 4) = *(const float4*)&As[kk][tr + 4];
            *(float4*)(b)     = *(const float4*)&Bs[kk][tc];
            *(float4*)(b + 4) = *(const float4*)&Bs[kk][tc + 4];
#pragma unroll
            for (int i = 0; i < 8; ++i)
#pragma unroll
                for (int j = 0; j < 8; ++j)
                    acc[i][j] = fmaf(a[i], b[j], acc[i][j]);
        }
        __syncthreads();
    }

#pragma unroll
    for (int i = 0; i < 8; ++i) {
        float* Cp = C + (size_t)(bm0 + tr + i) * N + bn0 + tc;
        *(float4*)(Cp)     = make_float4(acc[i][0], acc[i][1], acc[i][2], acc[i][3]);
        *(float4*)(Cp + 4) = make_float4(acc[i][4], acc[i][5], acc[i][6], acc[i][7]);
    }
}

// ============================================================================
// RoPE + scatter: read QKV [B,S,3E], rotate pairs (2i,2i+1), fold 1/sqrt(D)
// into Q, write Q/K/V in [B,H,S,D] layout.
// ============================================================================
__global__ __launch_bounds__(256) void rope_scatter(
    const float* __restrict__ qkv, const float* __restrict__ fc,
    float* __restrict__ Q, float* __restrict__ K, float* __restrict__ V)
{
    int idx = blockIdx.x * blockDim.x + threadIdx.x;  // B*S*H*64 threads
    int i = idx & 63;
    int h = (idx >> 6) & 15;
    int s = (idx >> 10) & 2047;
    int b = idx >> 21;

    const float* row = qkv + (size_t)(b * S_ + s) * E3_;
    float2 q = *(const float2*)(row + h * D_ + 2 * i);
    float2 k = *(const float2*)(row + E_ + h * D_ + 2 * i);
    float2 v = *(const float2*)(row + 2 * E_ + h * D_ + 2 * i);

    float c = fc[s * 128 + 2 * i];
    float sn = fc[s * 128 + 2 * i + 1];
    const float sc = 0.08838834764831845f;  // 1/sqrt(128)

    float2 qo = make_float2((q.x * c - q.y * sn) * sc, (q.y * c + q.x * sn) * sc);
    float2 ko = make_float2(k.x * c - k.y * sn, k.y * c + k.x * sn);

    size_t o = ((size_t)((b * H_ + h) * S_) + s) * D_ + 2 * i;
    *(float2*)(Q + o) = qo;
    *(float2*)(K + o) = ko;
    *(float2*)(V + o) = v;
}

// ============================================================================
// Flash attention, causal, fp32. BM=128 queries per block, BN=64 keys/iter.
// 256 threads: S-tile microtile 8x4, O-tile microtile 8x8.
// smem: Qst[d][r] 64KB, Kst[d][c] 32KB, Vs[c][d] 32KB, Ps[r][68] 34KB.
// ============================================================================
#define FBM 128
#define FBN 64
#define PS_STRIDE 68
#define FLASH_SMEM ((D_ * FBM + D_ * FBN + FBN * D_ + FBM * PS_STRIDE) * 4)

__global__ __launch_bounds__(256) void flash_causal(
    const float* __restrict__ Qg, const float* __restrict__ Kg,
    const float* __restrict__ Vg, float* __restrict__ Og)
{
    extern __shared__ float sm[];
    float* Qst = sm;                 // [D_][FBM]
    float* Kst = Qst + D_ * FBM;     // [D_][FBN]
    float* Vs  = Kst + D_ * FBN;     // [FBN][D_]
    float* Ps  = Vs + FBN * D_;      // [FBM][PS_STRIDE]

    const int tid = threadIdx.x;
    const int b = blockIdx.z, h = blockIdx.y, qt = blockIdx.x;
    const int q0 = qt * FBM;
    const size_t base = (size_t)(b * H_ + h) * S_ * D_;

    // load Q tile transposed: Qst[d][r]
    for (int idx = tid; idx < FBM * 32; idx += 256) {
        int r = idx & 127, d4 = idx >> 7;
        float4 v = *(const float4*)(Qg + base + (size_t)(q0 + r) * D_ + d4 * 4);
        Qst[(d4 * 4 + 0) * FBM + r] = v.x;
        Qst[(d4 * 4 + 1) * FBM + r] = v.y;
        Qst[(d4 * 4 + 2) * FBM + r] = v.z;
        Qst[(d4 * 4 + 3) * FBM + r] = v.w;
    }

    const int tr  = (tid >> 4) * 8;   // S rows == O rows
    const int tc  = (tid & 15) * 4;   // S cols
    const int tcO = (tid & 15) * 8;   // O cols

    float m[8], l[8], accO[8][8];
#pragma unroll
    for (int i = 0; i < 8; ++i) {
        m[i] = -3.0e38f;
        l[i] = 0.f;
#pragma unroll
        for (int j = 0; j < 8; ++j) accO[i][j] = 0.f;
    }

    const int nkt = 2 * qt + 1;  // last key tile index
    for (int kt = 0; kt <= nkt; ++kt) {
        const int k0 = kt * FBN;
        __syncthreads();  // protect Kst/Vs/Ps from previous iteration readers

        // K tile transposed: Kst[d][c]
        for (int idx = tid; idx < FBN * 32; idx += 256) {
            int r = idx & 63, d4 = idx >> 6;
            float4 v = *(const float4*)(Kg + base + (size_t)(k0 + r) * D_ + d4 * 4);
            Kst[(d4 * 4 + 0) * FBN + r] = v.x;
            Kst[(d4 * 4 + 1) * FBN + r] = v.y;
            Kst[(d4 * 4 + 2) * FBN + r] = v.z;
            Kst[(d4 * 4 + 3) * FBN + r] = v.w;
        }
        // V tile direct: Vs[c][d]
        for (int idx = tid; idx < FBN * 32; idx += 256) {
            int r = idx >> 5, d4 = idx & 31;
            *(float4*)&Vs[r * D_ + d4 * 4] =
                *(const float4*)(Vg + base + (size_t)(k0 + r) * D_ + d4 * 4);
        }
        __syncthreads();

        // ---- S = Q @ K^T (scale already folded into Q) ----
        float acc[8][4];
#pragma unroll
        for (int i = 0; i < 8; ++i)
#pragma unroll
            for (int j = 0; j < 4; ++j) acc[i][j] = 0.f;

#pragma unroll 4
        for (int kk = 0; kk < D_; ++kk) {
            float a[8], bc[4];
            *(float4*)(a)     = *(const float4*)&Qst[kk * FBM + tr];
            *(float4*)(a + 4) = *(const float4*)&Qst[kk * FBM + tr + 4];
            *(float4*)(bc)    = *(const float4*)&Kst[kk * FBN + tc];
#pragma unroll
            for (int i = 0; i < 8; ++i)
#pragma unroll
                for (int j = 0; j < 4; ++j)
                    acc[i][j] = fmaf(a[i], bc[j], acc[i][j]);
        }

        // ---- causal mask (only partially-valid tiles) ----
        if (k0 + FBN - 1 > q0) {
#pragma unroll
            for (int i = 0; i < 8; ++i)
#pragma unroll
                for (int j = 0; j < 4; ++j)
                    if (k0 + tc + j > q0 + tr + i) acc[i][j] = -1.0e30f;
        }

        // ---- online softmax (row groups of 16 lanes) ----
#pragma unroll
        for (int i = 0; i < 8; ++i) {
            float mx = fmaxf(fmaxf(acc[i][0], acc[i][1]), fmaxf(acc[i][2], acc[i][3]));
            mx = fmaxf(mx, __shfl_xor_sync(0xffffffffu, mx, 8));
            mx = fmaxf(mx, __shfl_xor_sync(0xffffffffu, mx, 4));
            mx = fmaxf(mx, __shfl_xor_sync(0xffffffffu, mx, 2));
            mx = fmaxf(mx, __shfl_xor_sync(0xffffffffu, mx, 1));
            float mn = fmaxf(m[i], mx);
            float alpha = __expf(m[i] - mn);
            m[i] = mn;
            float s = 0.f;
#pragma unroll
            for (int j = 0; j < 4; ++j) {
                float p = __expf(acc[i][j] - mn);
                acc[i][j] = p;
                s += p;
            }
            s += __shfl_xor_sync(0xffffffffu, s, 8);
            s += __shfl_xor_sync(0xffffffffu, s, 4);
            s += __shfl_xor_sync(0xffffffffu, s, 2);
            s += __shfl_xor_sync(0xffffffffu, s, 1);
            l[i] = l[i] * alpha + s;
#pragma unroll
            for (int j = 0; j < 8; ++j) accO[i][j] *= alpha;
            *(float4*)&Ps[(tr + i) * PS_STRIDE + tc] =
                make_float4(acc[i][0], acc[i][1], acc[i][2], acc[i][3]);
        }
        __syncthreads();

        // ---- O += P @ V ----
#pragma unroll 2
        for (int kk = 0; kk < FBN; ++kk) {
            float vb[8], pa[8];
            *(float4*)(vb)     = *(const float4*)&Vs[kk * D_ + tcO];
            *(float4*)(vb + 4) = *(const float4*)&Vs[kk * D_ + tcO + 4];
#pragma unroll
            for (int i = 0; i < 8; ++i) pa[i] = Ps[(tr + i) * PS_STRIDE + kk];
#pragma unroll
            for (int i = 0; i < 8; ++i)
#pragma unroll
                for (int j = 0; j < 8; ++j)
                    accO[i][j] = fmaf(pa[i], vb[j], accO[i][j]);
        }
    }

    // ---- epilogue: normalize, write [B,S,H,D] (== [B,S,E]) ----
#pragma unroll
    for (int i = 0; i < 8; ++i) {
        float inv = 1.f / l[i];
        int s = q0 + tr + i;
        float* Op = Og + (size_t)(b * S_ + s) * E_ + h * D_ + tcO;
        *(float4*)(Op) = make_float4(accO[i][0] * inv, accO[i][1] * inv,
                                     accO[i][2] * inv, accO[i][3] * inv);
        *(float4*)(Op + 4) = make_float4(accO[i][4] * inv, accO[i][5] * inv,
                                         accO[i][6] * inv, accO[i][7] * inv);
    }
}

// ============================================================================
// kernel_launch
// ============================================================================
extern "C" void kernel_launch(void* const* d_in, const int* in_sizes, int n_in,
                              void* d_out, int out_size)
{
    const float* x    = (const float*)d_in[0];  // [B,S,E]
    const float* Wqkv = (const float*)d_in[1];  // [E,3E]
    const float* Wo   = (const float*)d_in[2];  // [E,E]
    const float* fc   = (const float*)d_in[3];  // [S,1,D/2,2]
    float* out = (float*)d_out;

    float *qkv, *Q, *K, *V, *AO;
    cudaGetSymbolAddress((void**)&qkv, g_qkv);
    cudaGetSymbolAddress((void**)&Q, g_q);
    cudaGetSymbolAddress((void**)&K, g_k);
    cudaGetSymbolAddress((void**)&V, g_v);
    cudaGetSymbolAddress((void**)&AO, g_ao);

    // 1) QKV = x @ Wqkv
    {
        dim3 grid(E3_ / 128, (B_ * S_) / 128);
        sgemm128<<<grid, 256>>>(x, Wqkv, qkv, B_ * S_, E3_, E_);
    }
    // 2) RoPE + scatter to [B,H,S,D]
    {
        int total = B_ * S_ * H_ * (D_ / 2);
        rope_scatter<<<total / 256, 256>>>(qkv, fc, Q, K, V);
    }
    // 3) causal flash attention
    {
        cudaFuncSetAttribute(flash_causal,
                             cudaFuncAttributeMaxDynamicSharedMemorySize, FLASH_SMEM);
        dim3 grid(S_ / FBM, H_, B_);
        flash_causal<<<grid, 256, FLASH_SMEM>>>(Q, K, V, AO);
    }
    // 4) out = AO @ Wo
    {
        dim3 grid(E_ / 128, (B_ * S_) / 128);
        sgemm128<<<grid, 256>>>(AO, Wo, out, B_ * S_, E_, E_);
    }
}

// round 4
// speedup vs baseline: 1.9421x; 1.9421x over previous
#include <cuda_runtime.h>
#include <cstdint>
#include <math.h>

#define B_  2
#define S_  2048
#define E_  2048
#define H_  16
#define D_  128
#define E3_ 6144

// ---------------- scratch ----------------
__device__ float g_qkv[B_ * S_ * E3_];      // QKV GEMM output  [B,S,3E]
__device__ float g_xr [B_ * S_ * E_];       // tf32-rounded x
__device__ float g_wqkvT[E3_ * E_];         // Wqkv^T [3E, E], tf32-rounded
__device__ float g_woT [E_ * E_];           // Wo^T   [E, E],  tf32-rounded
__device__ float g_q[B_ * H_ * S_ * D_];
__device__ float g_k[B_ * H_ * S_ * D_];
__device__ float g_v[B_ * H_ * S_ * D_];
__device__ float g_ao[B_ * S_ * E_];        // attention out (tf32-rounded)

// ---------------- helpers ----------------
__device__ __forceinline__ uint32_t smem_u32(const void* p) {
    uint32_t a;
    asm("{ .reg .u64 t; cvta.to.shared.u64 t, %1; cvt.u32.u64 %0, t; }" : "=r"(a) : "l"(p));
    return a;
}
__device__ __forceinline__ float tf32_rn(float x) {
    uint32_t u;
    asm("cvt.rna.tf32.f32 %0, %1;" : "=r"(u) : "f"(x));
    return __uint_as_float(u);
}

#define CP_ASYNC16(sa, gp) \
    asm volatile("cp.async.cg.shared.global [%0], [%1], 16;" :: "r"(sa), "l"(gp))
#define CP_COMMIT() asm volatile("cp.async.commit_group;" ::: "memory")
#define CP_WAIT1()  asm volatile("cp.async.wait_group 1;" ::: "memory")

__device__ __forceinline__ void mma_tf32_16n8k8(
    float& c0, float& c1, float& c2, float& c3,
    uint32_t a0, uint32_t a1, uint32_t a2, uint32_t a3,
    uint32_t b0, uint32_t b1)
{
    asm volatile(
        "mma.sync.aligned.m16n8k8.row.col.f32.tf32.tf32.f32 "
        "{%0,%1,%2,%3}, {%4,%5,%6,%7}, {%8,%9}, {%0,%1,%2,%3};"
        : "+f"(c0), "+f"(c1), "+f"(c2), "+f"(c3)
        : "r"(a0), "r"(a1), "r"(a2), "r"(a3), "r"(b0), "r"(b1));
}

// ============================================================================
// tf32 mma.sync GEMM: C[M,Ntot] = A[M,K] @ Bt[Ntot,K]^T
// Block 128x128, BK=32, 8 warps (warp tile 64x32), 3-stage cp.async pipeline.
// Smem rows padded to 36 floats -> conflict-free 32-bit fragment loads.
// Inputs must already be tf32-rounded (bits passed straight to mma).
// ============================================================================
#define GPAD 36
#define GSTAGE (128 * GPAD)              // floats per operand per stage
#define GEMM_SMEM (3 * 2 * GSTAGE * 4)   // 3 stages * (A+B) * 4B = 110592B

__global__ __launch_bounds__(256, 1) void gemm_mma(
    const float* __restrict__ A, const float* __restrict__ Bt,
    float* __restrict__ C, int M, int Ntot, int K)
{
    extern __shared__ float sm[];
    // stage s: A at sm + s*2*GSTAGE, B at +GSTAGE

    const int tid  = threadIdx.x;
    const int wid  = tid >> 5;
    const int lane = tid & 31;
    const int gid  = lane >> 2;     // group id (0..7)
    const int tig  = lane & 3;      // thread in group
    const int wm   = wid & 1;       // warp row (0..1) -> 64 rows
    const int wn   = wid >> 1;      // warp col (0..3) -> 32 cols
    const int m0 = blockIdx.y * 128;
    const int n0 = blockIdx.x * 128;

    const int r_ld = tid >> 3;      // 0..31 (row group for loads, 4 iters x 32)
    const int c_ld = tid & 7;       // 16B chunk 0..7

    float c[4][4][4];
#pragma unroll
    for (int i = 0; i < 4; ++i)
#pragma unroll
        for (int j = 0; j < 4; ++j)
#pragma unroll
            for (int t = 0; t < 4; ++t) c[i][j][t] = 0.f;

    auto load_stage = [&](int kc, int slot) {
        float* As = sm + slot * 2 * GSTAGE;
        float* Bs = As + GSTAGE;
        const float* Ag = A + (size_t)m0 * K + kc * 32;
        const float* Bg = Bt + (size_t)n0 * K + kc * 32;
#pragma unroll
        for (int j = 0; j < 4; ++j) {
            int r = r_ld + j * 32;
            uint32_t sa = smem_u32(As + r * GPAD + c_ld * 4);
            CP_ASYNC16(sa, Ag + (size_t)r * K + c_ld * 4);
        }
#pragma unroll
        for (int j = 0; j < 4; ++j) {
            int r = r_ld + j * 32;
            uint32_t sb = smem_u32(Bs + r * GPAD + c_ld * 4);
            CP_ASYNC16(sb, Bg + (size_t)r * K + c_ld * 4);
        }
    };

    const int nk = K >> 5;  // BK=32 chunks

    load_stage(0, 0); CP_COMMIT();
    load_stage(1, 1); CP_COMMIT();

    for (int kc = 0; kc < nk; ++kc) {
        CP_WAIT1();
        __syncthreads();
        if (kc + 2 < nk) { load_stage(kc + 2, (kc + 2) % 3); CP_COMMIT(); }

        const float* As = sm + (kc % 3) * 2 * GSTAGE;
        const float* Bs = As + GSTAGE;
        const float* Aw = As + (wm * 64 + gid) * GPAD;        // + mt*16 rows
        const float* Bw = Bs + (wn * 32 + gid) * GPAD;        // + nt*8 rows

#pragma unroll
        for (int ks = 0; ks < 4; ++ks) {
            const int k0 = ks * 8;
            uint32_t a[4][4], b[4][2];
#pragma unroll
            for (int mt = 0; mt < 4; ++mt) {
                const float* p = Aw + mt * 16 * GPAD + k0;
                a[mt][0] = __float_as_uint(p[tig]);
                a[mt][1] = __float_as_uint(p[8 * GPAD + tig]);
                a[mt][2] = __float_as_uint(p[tig + 4]);
                a[mt][3] = __float_as_uint(p[8 * GPAD + tig + 4]);
            }
#pragma unroll
            for (int nt = 0; nt < 4; ++nt) {
                const float* p = Bw + nt * 8 * GPAD + k0;
                b[nt][0] = __float_as_uint(p[tig]);
                b[nt][1] = __float_as_uint(p[tig + 4]);
            }
#pragma unroll
            for (int mt = 0; mt < 4; ++mt)
#pragma unroll
                for (int nt = 0; nt < 4; ++nt)
                    mma_tf32_16n8k8(c[mt][nt][0], c[mt][nt][1], c[mt][nt][2], c[mt][nt][3],
                                    a[mt][0], a[mt][1], a[mt][2], a[mt][3],
                                    b[nt][0], b[nt][1]);
        }
        __syncthreads();
    }

    // epilogue
#pragma unroll
    for (int mt = 0; mt < 4; ++mt) {
        int r0 = m0 + wm * 64 + mt * 16 + gid;
#pragma unroll
        for (int nt = 0; nt < 4; ++nt) {
            int col = n0 + wn * 32 + nt * 8 + 2 * tig;
            *(float2*)(C + (size_t)r0 * Ntot + col) = make_float2(c[mt][nt][0], c[mt][nt][1]);
            *(float2*)(C + (size_t)(r0 + 8) * Ntot + col) = make_float2(c[mt][nt][2], c[mt][nt][3]);
        }
    }
}

// ============================================================================
// prep kernels
// ============================================================================
__global__ __launch_bounds__(256) void round_copy(const float* __restrict__ in,
                                                  float* __restrict__ out) {
    int i = blockIdx.x * 256 + threadIdx.x;
    float4 v = ((const float4*)in)[i];
    v.x = tf32_rn(v.x); v.y = tf32_rn(v.y); v.z = tf32_rn(v.z); v.w = tf32_rn(v.w);
    ((float4*)out)[i] = v;
}

// W[K][N] -> Wt[N][K], tf32-rounded
__global__ __launch_bounds__(256) void transpose_round(
    const float* __restrict__ W, float* __restrict__ Wt, int K, int N)
{
    __shared__ float t[32][33];
    int n0 = blockIdx.x * 32, k0 = blockIdx.y * 32;
    int tx = threadIdx.x & 31, ty = threadIdx.x >> 5;  // 32 x 8
#pragma unroll
    for (int j = 0; j < 4; ++j)
        t[ty + j * 8][tx] = W[(size_t)(k0 + ty + j * 8) * N + n0 + tx];
    __syncthreads();
#pragma unroll
    for (int j = 0; j < 4; ++j)
        Wt[(size_t)(n0 + ty + j * 8) * K + k0 + tx] = tf32_rn(t[tx][ty + j * 8]);
}

// ============================================================================
// RoPE + scatter
// ============================================================================
__global__ __launch_bounds__(256) void rope_scatter(
    const float* __restrict__ qkv, const float* __restrict__ fc,
    float* __restrict__ Q, float* __restrict__ K, float* __restrict__ V)
{
    int idx = blockIdx.x * blockDim.x + threadIdx.x;
    int i = idx & 63;
    int h = (idx >> 6) & 15;
    int s = (idx >> 10) & 2047;
    int b = idx >> 21;

    const float* row = qkv + (size_t)(b * S_ + s) * E3_;
    float2 q = *(const float2*)(row + h * D_ + 2 * i);
    float2 k = *(const float2*)(row + E_ + h * D_ + 2 * i);
    float2 v = *(const float2*)(row + 2 * E_ + h * D_ + 2 * i);

    float c = fc[s * 128 + 2 * i];
    float sn = fc[s * 128 + 2 * i + 1];
    const float sc = 0.08838834764831845f;  // 1/sqrt(128)

    float2 qo = make_float2((q.x * c - q.y * sn) * sc, (q.y * c + q.x * sn) * sc);
    float2 ko = make_float2(k.x * c - k.y * sn, k.y * c + k.x * sn);

    size_t o = ((size_t)((b * H_ + h) * S_) + s) * D_ + 2 * i;
    *(float2*)(Q + o) = qo;
    *(float2*)(K + o) = ko;
    *(float2*)(V + o) = v;
}

// ============================================================================
// Flash attention, causal, fp32 SIMT (AO written tf32-rounded)
// ============================================================================
#define FBM 128
#define FBN 64
#define PS_STRIDE 68
#define FLASH_SMEM ((D_ * FBM + D_ * FBN + FBN * D_ + FBM * PS_STRIDE) * 4)

__global__ __launch_bounds__(256) void flash_causal(
    const float* __restrict__ Qg, const float* __restrict__ Kg,
    const float* __restrict__ Vg, float* __restrict__ Og)
{
    extern __shared__ float smf[];
    float* Qst = smf;
    float* Kst = Qst + D_ * FBM;
    float* Vs  = Kst + D_ * FBN;
    float* Ps  = Vs + FBN * D_;

    const int tid = threadIdx.x;
    const int b = blockIdx.z, h = blockIdx.y, qt = blockIdx.x;
    const int q0 = qt * FBM;
    const size_t base = (size_t)(b * H_ + h) * S_ * D_;

    for (int idx = tid; idx < FBM * 32; idx += 256) {
        int r = idx & 127, d4 = idx >> 7;
        float4 v = *(const float4*)(Qg + base + (size_t)(q0 + r) * D_ + d4 * 4);
        Qst[(d4 * 4 + 0) * FBM + r] = v.x;
        Qst[(d4 * 4 + 1) * FBM + r] = v.y;
        Qst[(d4 * 4 + 2) * FBM + r] = v.z;
        Qst[(d4 * 4 + 3) * FBM + r] = v.w;
    }

    const int tr  = (tid >> 4) * 8;
    const int tc  = (tid & 15) * 4;
    const int tcO = (tid & 15) * 8;

    float m[8], l[8], accO[8][8];
#pragma unroll
    for (int i = 0; i < 8; ++i) {
        m[i] = -3.0e38f;
        l[i] = 0.f;
#pragma unroll
        for (int j = 0; j < 8; ++j) accO[i][j] = 0.f;
    }

    const int nkt = 2 * qt + 1;
    for (int kt = 0; kt <= nkt; ++kt) {
        const int k0 = kt * FBN;
        __syncthreads();

        for (int idx = tid; idx < FBN * 32; idx += 256) {
            int r = idx & 63, d4 = idx >> 6;
            float4 v = *(const float4*)(Kg + base + (size_t)(k0 + r) * D_ + d4 * 4);
            Kst[(d4 * 4 + 0) * FBN + r] = v.x;
            Kst[(d4 * 4 + 1) * FBN + r] = v.y;
            Kst[(d4 * 4 + 2) * FBN + r] = v.z;
            Kst[(d4 * 4 + 3) * FBN + r] = v.w;
        }
        for (int idx = tid; idx < FBN * 32; idx += 256) {
            int r = idx >> 5, d4 = idx & 31;
            *(float4*)&Vs[r * D_ + d4 * 4] =
                *(const float4*)(Vg + base + (size_t)(k0 + r) * D_ + d4 * 4);
        }
        __syncthreads();

        float acc[8][4];
#pragma unroll
        for (int i = 0; i < 8; ++i)
#pragma unroll
            for (int j = 0; j < 4; ++j) acc[i][j] = 0.f;

#pragma unroll 4
        for (int kk = 0; kk < D_; ++kk) {
            float a[8], bc[4];
            *(float4*)(a)     = *(const float4*)&Qst[kk * FBM + tr];
            *(float4*)(a + 4) = *(const float4*)&Qst[kk * FBM + tr + 4];
            *(float4*)(bc)    = *(const float4*)&Kst[kk * FBN + tc];
#pragma unroll
            for (int i = 0; i < 8; ++i)
#pragma unroll
                for (int j = 0; j < 4; ++j)
                    acc[i][j] = fmaf(a[i], bc[j], acc[i][j]);
        }

        if (k0 + FBN - 1 > q0) {
#pragma unroll
            for (int i = 0; i < 8; ++i)
#pragma unroll
                for (int j = 0; j < 4; ++j)
                    if (k0 + tc + j > q0 + tr + i) acc[i][j] = -1.0e30f;
        }

#pragma unroll
        for (int i = 0; i < 8; ++i) {
            float mx = fmaxf(fmaxf(acc[i][0], acc[i][1]), fmaxf(acc[i][2], acc[i][3]));
            mx = fmaxf(mx, __shfl_xor_sync(0xffffffffu, mx, 8));
            mx = fmaxf(mx, __shfl_xor_sync(0xffffffffu, mx, 4));
            mx = fmaxf(mx, __shfl_xor_sync(0xffffffffu, mx, 2));
            mx = fmaxf(mx, __shfl_xor_sync(0xffffffffu, mx, 1));
            float mn = fmaxf(m[i], mx);
            float alpha = __expf(m[i] - mn);
            m[i] = mn;
            float s = 0.f;
#pragma unroll
            for (int j = 0; j < 4; ++j) {
                float p = __expf(acc[i][j] - mn);
                acc[i][j] = p;
                s += p;
            }
            s += __shfl_xor_sync(0xffffffffu, s, 8);
            s += __shfl_xor_sync(0xffffffffu, s, 4);
            s += __shfl_xor_sync(0xffffffffu, s, 2);
            s += __shfl_xor_sync(0xffffffffu, s, 1);
            l[i] = l[i] * alpha + s;
#pragma unroll
            for (int j = 0; j < 8; ++j) accO[i][j] *= alpha;
            *(float4*)&Ps[(tr + i) * PS_STRIDE + tc] =
                make_float4(acc[i][0], acc[i][1], acc[i][2], acc[i][3]);
        }
        __syncthreads();

#pragma unroll 2
        for (int kk = 0; kk < FBN; ++kk) {
            float vb[8], pa[8];
            *(float4*)(vb)     = *(const float4*)&Vs[kk * D_ + tcO];
            *(float4*)(vb + 4) = *(const float4*)&Vs[kk * D_ + tcO + 4];
#pragma unroll
            for (int i = 0; i < 8; ++i) pa[i] = Ps[(tr + i) * PS_STRIDE + kk];
#pragma unroll
            for (int i = 0; i < 8; ++i)
#pragma unroll
                for (int j = 0; j < 8; ++j)
                    accO[i][j] = fmaf(pa[i], vb[j], accO[i][j]);
        }
    }

#pragma unroll
    for (int i = 0; i < 8; ++i) {
        float inv = 1.f / l[i];
        int s = q0 + tr + i;
        float* Op = Og + (size_t)(b * S_ + s) * E_ + h * D_ + tcO;
        *(float4*)(Op) = make_float4(tf32_rn(accO[i][0] * inv), tf32_rn(accO[i][1] * inv),
                                     tf32_rn(accO[i][2] * inv), tf32_rn(accO[i][3] * inv));
        *(float4*)(Op + 4) = make_float4(tf32_rn(accO[i][4] * inv), tf32_rn(accO[i][5] * inv),
                                         tf32_rn(accO[i][6] * inv), tf32_rn(accO[i][7] * inv));
    }
}

// ============================================================================
// kernel_launch
// ============================================================================
extern "C" void kernel_launch(void* const* d_in, const int* in_sizes, int n_in,
                              void* d_out, int out_size)
{
    const float* x    = (const float*)d_in[0];
    const float* Wqkv = (const float*)d_in[1];
    const float* Wo   = (const float*)d_in[2];
    const float* fc   = (const float*)d_in[3];
    float* out = (float*)d_out;

    float *qkv, *xr, *wqkvT, *woT, *Q, *K, *V, *AO;
    cudaGetSymbolAddress((void**)&qkv, g_qkv);
    cudaGetSymbolAddress((void**)&xr, g_xr);
    cudaGetSymbolAddress((void**)&wqkvT, g_wqkvT);
    cudaGetSymbolAddress((void**)&woT, g_woT);
    cudaGetSymbolAddress((void**)&Q, g_q);
    cudaGetSymbolAddress((void**)&K, g_k);
    cudaGetSymbolAddress((void**)&V, g_v);
    cudaGetSymbolAddress((void**)&AO, g_ao);

    cudaFuncSetAttribute(gemm_mma, cudaFuncAttributeMaxDynamicSharedMemorySize, GEMM_SMEM);
    cudaFuncSetAttribute(flash_causal, cudaFuncAttributeMaxDynamicSharedMemorySize, FLASH_SMEM);

    // prep: tf32-round x; transpose+round weights
    round_copy<<<(B_ * S_ * E_) / 4 / 256, 256>>>(x, xr);
    {
        dim3 g(E3_ / 32, E_ / 32);
        transpose_round<<<g, 256>>>(Wqkv, wqkvT, E_, E3_);
    }
    {
        dim3 g(E_ / 32, E_ / 32);
        transpose_round<<<g, 256>>>(Wo, woT, E_, E_);
    }

    // 1) QKV = xr @ WqkvT^T
    {
        dim3 grid(E3_ / 128, (B_ * S_) / 128);
        gemm_mma<<<grid, 256, GEMM_SMEM>>>(xr, wqkvT, qkv, B_ * S_, E3_, E_);
    }
    // 2) RoPE + scatter
    {
        int total = B_ * S_ * H_ * (D_ / 2);
        rope_scatter<<<total / 256, 256>>>(qkv, fc, Q, K, V);
    }
    // 3) causal flash attention
    {
        dim3 grid(S_ / FBM, H_, B_);
        flash_causal<<<grid, 256, FLASH_SMEM>>>(Q, K, V, AO);
    }
    // 4) out = AO @ WoT^T
    {
        dim3 grid(E_ / 128, (B_ * S_) / 128);
        gemm_mma<<<grid, 256, GEMM_SMEM>>>(AO, woT, out, B_ * S_, E_, E_);
    }
}

// round 6
// speedup vs baseline: 3.1643x; 1.6293x over previous
#include <cuda_runtime.h>
#include <cstdint>
#include <math.h>

#define B_  2
#define S_  2048
#define E_  2048
#define H_  16
#define D_  128
#define E3_ 6144

// ---------------- scratch ----------------
__device__ float g_qkv[B_ * S_ * E3_];
__device__ float g_xr [B_ * S_ * E_];
__device__ float g_wqkvT[E3_ * E_];
__device__ float g_woT [E_ * E_];
__device__ float g_q[B_ * H_ * S_ * D_];   // d-interleaved, tf32, scaled
__device__ float g_k[B_ * H_ * S_ * D_];   // d-interleaved, tf32
__device__ float g_v[B_ * H_ * S_ * D_];   // natural, tf32
__device__ float g_ao[B_ * S_ * E_];

// ---------------- helpers ----------------
__device__ __forceinline__ uint32_t smem_u32(const void* p) {
    uint32_t a;
    asm("{ .reg .u64 t; cvta.to.shared.u64 t, %1; cvt.u32.u64 %0, t; }" : "=r"(a) : "l"(p));
    return a;
}
__device__ __forceinline__ float tf32_rn(float x) {
    uint32_t u;
    asm("cvt.rna.tf32.f32 %0, %1;" : "=r"(u) : "f"(x));
    return __uint_as_float(u);
}

#define CP_ASYNC16(sa, gp) \
    asm volatile("cp.async.cg.shared.global [%0], [%1], 16;" :: "r"(sa), "l"(gp))
#define CP_COMMIT() asm volatile("cp.async.commit_group;" ::: "memory")
#define CP_WAIT1()  asm volatile("cp.async.wait_group 1;" ::: "memory")
#define CP_WAIT0()  asm volatile("cp.async.wait_group 0;" ::: "memory")

__device__ __forceinline__ void mma_tf32_16n8k8(
    float& c0, float& c1, float& c2, float& c3,
    uint32_t a0, uint32_t a1, uint32_t a2, uint32_t a3,
    uint32_t b0, uint32_t b1)
{
    asm volatile(
        "mma.sync.aligned.m16n8k8.row.col.f32.tf32.tf32.f32 "
        "{%0,%1,%2,%3}, {%4,%5,%6,%7}, {%8,%9}, {%0,%1,%2,%3};"
        : "+f"(c0), "+f"(c1), "+f"(c2), "+f"(c3)
        : "r"(a0), "r"(a1), "r"(a2), "r"(a3), "r"(b0), "r"(b1));
}

// ============================================================================
// tf32 mma.sync dense GEMM (unchanged — validated R4)
// ============================================================================
#define GPAD 36
#define GSTAGE (128 * GPAD)
#define GEMM_SMEM (3 * 2 * GSTAGE * 4)

__global__ __launch_bounds__(256, 1) void gemm_mma(
    const float* __restrict__ A, const float* __restrict__ Bt,
    float* __restrict__ C, int M, int Ntot, int K)
{
    extern __shared__ float sm[];
    const int tid  = threadIdx.x;
    const int wid  = tid >> 5;
    const int lane = tid & 31;
    const int gid  = lane >> 2;
    const int tig  = lane & 3;
    const int wm   = wid & 1;
    const int wn   = wid >> 1;
    const int m0 = blockIdx.y * 128;
    const int n0 = blockIdx.x * 128;

    const int r_ld = tid >> 3;
    const int c_ld = tid & 7;

    float c[4][4][4];
#pragma unroll
    for (int i = 0; i < 4; ++i)
#pragma unroll
        for (int j = 0; j < 4; ++j)
#pragma unroll
            for (int t = 0; t < 4; ++t) c[i][j][t] = 0.f;

    auto load_stage = [&](int kc, int slot) {
        float* As = sm + slot * 2 * GSTAGE;
        float* Bs = As + GSTAGE;
        const float* Ag = A + (size_t)m0 * K + kc * 32;
        const float* Bg = Bt + (size_t)n0 * K + kc * 32;
#pragma unroll
        for (int j = 0; j < 4; ++j) {
            int r = r_ld + j * 32;
            CP_ASYNC16(smem_u32(As + r * GPAD + c_ld * 4), Ag + (size_t)r * K + c_ld * 4);
        }
#pragma unroll
        for (int j = 0; j < 4; ++j) {
            int r = r_ld + j * 32;
            CP_ASYNC16(smem_u32(Bs + r * GPAD + c_ld * 4), Bg + (size_t)r * K + c_ld * 4);
        }
    };

    const int nk = K >> 5;
    load_stage(0, 0); CP_COMMIT();
    load_stage(1, 1); CP_COMMIT();

    for (int kc = 0; kc < nk; ++kc) {
        CP_WAIT1();
        __syncthreads();
        if (kc + 2 < nk) { load_stage(kc + 2, (kc + 2) % 3); CP_COMMIT(); }

        const float* As = sm + (kc % 3) * 2 * GSTAGE;
        const float* Bs = As + GSTAGE;
        const float* Aw = As + (wm * 64 + gid) * GPAD;
        const float* Bw = Bs + (wn * 32 + gid) * GPAD;

#pragma unroll
        for (int ks = 0; ks < 4; ++ks) {
            const int k0 = ks * 8;
            uint32_t a[4][4], b[4][2];
#pragma unroll
            for (int mt = 0; mt < 4; ++mt) {
                const float* p = Aw + mt * 16 * GPAD + k0;
                a[mt][0] = __float_as_uint(p[tig]);
                a[mt][1] = __float_as_uint(p[8 * GPAD + tig]);
                a[mt][2] = __float_as_uint(p[tig + 4]);
                a[mt][3] = __float_as_uint(p[8 * GPAD + tig + 4]);
            }
#pragma unroll
            for (int nt = 0; nt < 4; ++nt) {
                const float* p = Bw + nt * 8 * GPAD + k0;
                b[nt][0] = __float_as_uint(p[tig]);
                b[nt][1] = __float_as_uint(p[tig + 4]);
            }
#pragma unroll
            for (int mt = 0; mt < 4; ++mt)
#pragma unroll
                for (int nt = 0; nt < 4; ++nt)
                    mma_tf32_16n8k8(c[mt][nt][0], c[mt][nt][1], c[mt][nt][2], c[mt][nt][3],
                                    a[mt][0], a[mt][1], a[mt][2], a[mt][3],
                                    b[nt][0], b[nt][1]);
        }
        __syncthreads();
    }

#pragma unroll
    for (int mt = 0; mt < 4; ++mt) {
        int r0 = m0 + wm * 64 + mt * 16 + gid;
#pragma unroll
        for (int nt = 0; nt < 4; ++nt) {
            int col = n0 + wn * 32 + nt * 8 + 2 * tig;
            *(float2*)(C + (size_t)r0 * Ntot + col) = make_float2(c[mt][nt][0], c[mt][nt][1]);
            *(float2*)(C + (size_t)(r0 + 8) * Ntot + col) = make_float2(c[mt][nt][2], c[mt][nt][3]);
        }
    }
}

// ============================================================================
// prep kernels
// ============================================================================
__global__ __launch_bounds__(256) void round_copy(const float* __restrict__ in,
                                                  float* __restrict__ out) {
    int i = blockIdx.x * 256 + threadIdx.x;
    float4 v = ((const float4*)in)[i];
    v.x = tf32_rn(v.x); v.y = tf32_rn(v.y); v.z = tf32_rn(v.z); v.w = tf32_rn(v.w);
    ((float4*)out)[i] = v;
}

__global__ __launch_bounds__(256) void transpose_round(
    const float* __restrict__ W, float* __restrict__ Wt, int K, int N)
{
    __shared__ float t[32][33];
    int n0 = blockIdx.x * 32, k0 = blockIdx.y * 32;
    int tx = threadIdx.x & 31, ty = threadIdx.x >> 5;
#pragma unroll
    for (int j = 0; j < 4; ++j)
        t[ty + j * 8][tx] = W[(size_t)(k0 + ty + j * 8) * N + n0 + tx];
    __syncthreads();
#pragma unroll
    for (int j = 0; j < 4; ++j)
        Wt[(size_t)(n0 + ty + j * 8) * K + k0 + tx] = tf32_rn(t[tx][ty + j * 8]);
}

// ============================================================================
// RoPE + scatter. Q,K written d-INTERLEAVED (within each 8-block, position p
// stored at ((p&3)<<1)|(p>>2&1)) and tf32-rounded; V natural, tf32-rounded.
// 1/sqrt(D) folded into Q.
// ============================================================================
__global__ __launch_bounds__(256) void rope_scatter(
    const float* __restrict__ qkv, const float* __restrict__ fc,
    float* __restrict__ Q, float* __restrict__ K, float* __restrict__ V)
{
    int idx = blockIdx.x * blockDim.x + threadIdx.x;
    int i = idx & 63;
    int h = (idx >> 6) & 15;
    int s = (idx >> 10) & 2047;
    int b = idx >> 21;

    const float* row = qkv + (size_t)(b * S_ + s) * E3_;
    float2 q = *(const float2*)(row + h * D_ + 2 * i);
    float2 k = *(const float2*)(row + E_ + h * D_ + 2 * i);
    float2 v = *(const float2*)(row + 2 * E_ + h * D_ + 2 * i);

    float c = fc[s * 128 + 2 * i];
    float sn = fc[s * 128 + 2 * i + 1];
    const float sc = 0.08838834764831845f;  // 1/sqrt(128)

    float q0v = tf32_rn((q.x * c - q.y * sn) * sc);
    float q1v = tf32_rn((q.y * c + q.x * sn) * sc);
    float k0v = tf32_rn(k.x * c - k.y * sn);
    float k1v = tf32_rn(k.y * c + k.x * sn);

    int d0 = 2 * i, d1 = 2 * i + 1;
    int p0 = (d0 & ~7) | (((d0 & 3) << 1) | ((d0 >> 2) & 1));
    int p1 = (d1 & ~7) | (((d1 & 3) << 1) | ((d1 >> 2) & 1));

    size_t o = ((size_t)((b * H_ + h) * S_) + s) * D_;
    Q[o + p0] = q0v; Q[o + p1] = q1v;
    K[o + p0] = k0v; K[o + p1] = k1v;
    *(float2*)(V + o + d0) = make_float2(tf32_rn(v.x), tf32_rn(v.y));
}

// ============================================================================
// Flash attention with tf32 mma.sync. BM=128, BN=64, 8 warps (16 rows each).
// Q A-fragments in registers; K double-buffered via cp.async (d-interleaved);
// V transposed+key-interleaved into smem; P staged key-interleaved in smem.
// ============================================================================
#define KSP 136
#define VSP 72
#define PSP 72
#define KS_F (64 * KSP)
#define VTS_F (128 * VSP)
#define PS_F (128 * PSP)
#define FL_SMEM ((2 * KS_F + 2 * VTS_F + PS_F) * 4)

__global__ __launch_bounds__(256, 1) void flash_mma(
    const float* __restrict__ Qg, const float* __restrict__ Kg,
    const float* __restrict__ Vg, float* __restrict__ Og)
{
    extern __shared__ float sm[];
    float* Ks  = sm;                 // [2][64][KSP]
    float* Vts = sm + 2 * KS_F;      // [2][128][VSP]  (Vts[d][ikey])
    float* Ps  = Vts + 2 * VTS_F;    // [128][PSP]

    const int tid  = threadIdx.x;
    const int wid  = tid >> 5;
    const int lane = tid & 31;
    const int gid  = lane >> 2;
    const int tig  = lane & 3;
    const int b = blockIdx.z, h = blockIdx.y;
    const int qt = (int)gridDim.x - 1 - (int)blockIdx.x;  // big tiles first
    const int q0 = qt * 128;
    const int wrow = wid * 16;
    const size_t base = (size_t)(b * H_ + h) * S_ * D_;

    // ---- Q fragments (one-time register load) ----
    float2 aq[16][2];
    {
        const float* Qp0 = Qg + base + (size_t)(q0 + wrow + gid) * D_ + 2 * tig;
        const float* Qp1 = Qp0 + 8 * D_;
#pragma unroll
        for (int ks = 0; ks < 16; ++ks) {
            aq[ks][0] = *(const float2*)(Qp0 + 8 * ks);
            aq[ks][1] = *(const float2*)(Qp1 + 8 * ks);
        }
    }

    float accO[16][4];
#pragma unroll
    for (int nt = 0; nt < 16; ++nt)
#pragma unroll
        for (int t = 0; t < 4; ++t) accO[nt][t] = 0.f;
    float mrow[2] = {-3.0e38f, -3.0e38f};
    float lrow[2] = {0.f, 0.f};

    // K tile: 64 rows x 128 d = 2048 float4s -> 8 iterations of 256 threads
    auto load_K = [&](int kt, int bf) {
        const float* Kgp = Kg + base + (size_t)kt * 64 * D_;
        float* dst = Ks + bf * KS_F;
#pragma unroll
        for (int j = 0; j < 8; ++j) {
            int q = tid + j * 256;
            int r = q >> 5, cc = q & 31;
            CP_ASYNC16(smem_u32(dst + r * KSP + cc * 4), Kgp + (size_t)r * D_ + cc * 4);
        }
    };
    auto load_V = [&](int kt, int bf) {
        const float* Vgp = Vg + base + (size_t)kt * 64 * D_;
        float* dst = Vts + bf * VTS_F;
#pragma unroll
        for (int j = 0; j < 8; ++j) {
            int e = tid + j * 256;         // 2048 float4s: key = e&63, d4 = e>>6
            int key = e & 63, d4 = e >> 6;
            float4 v = *(const float4*)(Vgp + (size_t)key * D_ + d4 * 4);
            int ik = (key & ~7) | (((key & 3) << 1) | ((key >> 2) & 1));
            dst[(d4 * 4 + 0) * VSP + ik] = v.x;
            dst[(d4 * 4 + 1) * VSP + ik] = v.y;
            dst[(d4 * 4 + 2) * VSP + ik] = v.z;
            dst[(d4 * 4 + 3) * VSP + ik] = v.w;
        }
    };

    const int nkt = 2 * qt + 1;
    load_K(0, 0); CP_COMMIT();
    load_V(0, 0);

    const int row0s = (wrow + gid) * PSP;
    const int row1s = row0s + 8 * PSP;
    // P store target slots for cols 2tig, 2tig+1 (key-interleaved)
    const int c0i = 2 * tig, c1i = 2 * tig + 1;
    const int j0 = ((c0i & 3) << 1) | ((c0i >> 2) & 1);
    const int j1 = ((c1i & 3) << 1) | ((c1i >> 2) & 1);

    for (int kt = 0; kt <= nkt; ++kt) {
        const int cur = kt & 1, nxt = cur ^ 1;
        if (kt < nkt) { load_K(kt + 1, nxt); CP_COMMIT(); CP_WAIT1(); }
        else         { CP_WAIT0(); }
        __syncthreads();   // A: Ks[cur] ready, Vts[cur] visible, Ps free

        // ---- S = Q @ K^T ----
        float sacc[8][4];
#pragma unroll
        for (int nt = 0; nt < 8; ++nt)
#pragma unroll
            for (int t = 0; t < 4; ++t) sacc[nt][t] = 0.f;

        const float* Kb = Ks + cur * KS_F + gid * KSP + 2 * tig;
#pragma unroll
        for (int ks = 0; ks < 16; ++ks) {
            uint32_t a0 = __float_as_uint(aq[ks][0].x);
            uint32_t a1 = __float_as_uint(aq[ks][1].x);
            uint32_t a2 = __float_as_uint(aq[ks][0].y);
            uint32_t a3 = __float_as_uint(aq[ks][1].y);
#pragma unroll
            for (int nt = 0; nt < 8; ++nt) {
                float2 bb = *(const float2*)(Kb + nt * 8 * KSP + ks * 8);
                mma_tf32_16n8k8(sacc[nt][0], sacc[nt][1], sacc[nt][2], sacc[nt][3],
                                a0, a1, a2, a3,
                                __float_as_uint(bb.x), __float_as_uint(bb.y));
            }
        }

        if (kt < nkt) load_V(kt + 1, nxt);

        // ---- causal mask ----
        const int k0 = kt * 64;
        if (k0 + 63 > q0 + wrow) {
            int r0 = q0 + wrow + gid, r1 = r0 + 8;
#pragma unroll
            for (int nt = 0; nt < 8; ++nt) {
                int cA = k0 + nt * 8 + 2 * tig, cB = cA + 1;
                if (cA > r0) sacc[nt][0] = -1.0e30f;
                if (cB > r0) sacc[nt][1] = -1.0e30f;
                if (cA > r1) sacc[nt][2] = -1.0e30f;
                if (cB > r1) sacc[nt][3] = -1.0e30f;
            }
        }

        // ---- online softmax (2 rows per thread) ----
        float mx0 = -3.0e38f, mx1 = -3.0e38f;
#pragma unroll
        for (int nt = 0; nt < 8; ++nt) {
            mx0 = fmaxf(mx0, fmaxf(sacc[nt][0], sacc[nt][1]));
            mx1 = fmaxf(mx1, fmaxf(sacc[nt][2], sacc[nt][3]));
        }
        mx0 = fmaxf(mx0, __shfl_xor_sync(0xffffffffu, mx0, 1));
        mx0 = fmaxf(mx0, __shfl_xor_sync(0xffffffffu, mx0, 2));
        mx1 = fmaxf(mx1, __shfl_xor_sync(0xffffffffu, mx1, 1));
        mx1 = fmaxf(mx1, __shfl_xor_sync(0xffffffffu, mx1, 2));

        float mn0 = fmaxf(mrow[0], mx0);
        float mn1 = fmaxf(mrow[1], mx1);
        float al0 = __expf(mrow[0] - mn0);
        float al1 = __expf(mrow[1] - mn1);
        mrow[0] = mn0; mrow[1] = mn1;

        float s0 = 0.f, s1 = 0.f;
#pragma unroll
        for (int nt = 0; nt < 8; ++nt) {
            sacc[nt][0] = __expf(sacc[nt][0] - mn0);
            sacc[nt][1] = __expf(sacc[nt][1] - mn0);
            sacc[nt][2] = __expf(sacc[nt][2] - mn1);
            sacc[nt][3] = __expf(sacc[nt][3] - mn1);
            s0 += sacc[nt][0] + sacc[nt][1];
            s1 += sacc[nt][2] + sacc[nt][3];
        }
        s0 += __shfl_xor_sync(0xffffffffu, s0, 1);
        s0 += __shfl_xor_sync(0xffffffffu, s0, 2);
        s1 += __shfl_xor_sync(0xffffffffu, s1, 1);
        s1 += __shfl_xor_sync(0xffffffffu, s1, 2);
        lrow[0] = lrow[0] * al0 + s0;
        lrow[1] = lrow[1] * al1 + s1;

#pragma unroll
        for (int nt = 0; nt < 16; ++nt) {
            accO[nt][0] *= al0; accO[nt][1] *= al0;
            accO[nt][2] *= al1; accO[nt][3] *= al1;
        }
        // P -> smem (tf32, key-interleaved)
#pragma unroll
        for (int nt = 0; nt < 8; ++nt) {
            int bb = nt * 8;
            Ps[row0s + bb + j0] = tf32_rn(sacc[nt][0]);
            Ps[row0s + bb + j1] = tf32_rn(sacc[nt][1]);
            Ps[row1s + bb + j0] = tf32_rn(sacc[nt][2]);
            Ps[row1s + bb + j1] = tf32_rn(sacc[nt][3]);
        }
        __syncthreads();   // B: Ps written, Vts[cur] ready

        // ---- O += P @ V ----
        const float* Vb = Vts + cur * VTS_F + gid * VSP + 2 * tig;
#pragma unroll
        for (int ks2 = 0; ks2 < 8; ++ks2) {
            float2 pa0 = *(const float2*)(Ps + row0s + ks2 * 8 + 2 * tig);
            float2 pa1 = *(const float2*)(Ps + row1s + ks2 * 8 + 2 * tig);
            uint32_t a0 = __float_as_uint(pa0.x);
            uint32_t a1 = __float_as_uint(pa1.x);
            uint32_t a2 = __float_as_uint(pa0.y);
            uint32_t a3 = __float_as_uint(pa1.y);
#pragma unroll
            for (int nt = 0; nt < 16; ++nt) {
                float2 vb = *(const float2*)(Vb + nt * 8 * VSP + ks2 * 8);
                mma_tf32_16n8k8(accO[nt][0], accO[nt][1], accO[nt][2], accO[nt][3],
                                a0, a1, a2, a3,
                                __float_as_uint(vb.x), __float_as_uint(vb.y));
            }
        }
    }

    // ---- epilogue ----
    float inv0 = 1.f / lrow[0];
    float inv1 = 1.f / lrow[1];
    int qrow = q0 + wrow + gid;
    float* O0 = Og + (size_t)(b * S_ + qrow) * E_ + h * D_ + 2 * tig;
    float* O1 = O0 + 8 * (size_t)E_;
#pragma unroll
    for (int nt = 0; nt < 16; ++nt) {
        *(float2*)(O0 + nt * 8) = make_float2(tf32_rn(accO[nt][0] * inv0),
                                              tf32_rn(accO[nt][1] * inv0));
        *(float2*)(O1 + nt * 8) = make_float2(tf32_rn(accO[nt][2] * inv1),
                                              tf32_rn(accO[nt][3] * inv1));
    }
}

// ============================================================================
// kernel_launch
// ============================================================================
extern "C" void kernel_launch(void* const* d_in, const int* in_sizes, int n_in,
                              void* d_out, int out_size)
{
    const float* x    = (const float*)d_in[0];
    const float* Wqkv = (const float*)d_in[1];
    const float* Wo   = (const float*)d_in[2];
    const float* fc   = (const float*)d_in[3];
    float* out = (float*)d_out;

    float *qkv, *xr, *wqkvT, *woT, *Q, *K, *V, *AO;
    cudaGetSymbolAddress((void**)&qkv, g_qkv);
    cudaGetSymbolAddress((void**)&xr, g_xr);
    cudaGetSymbolAddress((void**)&wqkvT, g_wqkvT);
    cudaGetSymbolAddress((void**)&woT, g_woT);
    cudaGetSymbolAddress((void**)&Q, g_q);
    cudaGetSymbolAddress((void**)&K, g_k);
    cudaGetSymbolAddress((void**)&V, g_v);
    cudaGetSymbolAddress((void**)&AO, g_ao);

    cudaFuncSetAttribute(gemm_mma, cudaFuncAttributeMaxDynamicSharedMemorySize, GEMM_SMEM);
    cudaFuncSetAttribute(flash_mma, cudaFuncAttributeMaxDynamicSharedMemorySize, FL_SMEM);

    round_copy<<<(B_ * S_ * E_) / 4 / 256, 256>>>(x, xr);
    {
        dim3 g(E3_ / 32, E_ / 32);
        transpose_round<<<g, 256>>>(Wqkv, wqkvT, E_, E3_);
    }
    {
        dim3 g(E_ / 32, E_ / 32);
        transpose_round<<<g, 256>>>(Wo, woT, E_, E_);
    }

    // 1) QKV = xr @ WqkvT^T
    {
        dim3 grid(E3_ / 128, (B_ * S_) / 128);
        gemm_mma<<<grid, 256, GEMM_SMEM>>>(xr, wqkvT, qkv, B_ * S_, E3_, E_);
    }
    // 2) RoPE + scatter (interleaved/rounded)
    {
        int total = B_ * S_ * H_ * (D_ / 2);
        rope_scatter<<<total / 256, 256>>>(qkv, fc, Q, K, V);
    }
    // 3) flash attention (tensor cores)
    {
        dim3 grid(S_ / 128, H_, B_);
        flash_mma<<<grid, 256, FL_SMEM>>>(Q, K, V, AO);
    }
    // 4) out = AO @ WoT^T
    {
        dim3 grid(E_ / 128, (B_ * S_) / 128);
        gemm_mma<<<grid, 256, GEMM_SMEM>>>(AO, woT, out, B_ * S_, E_, E_);
    }
}

// round 7
// speedup vs baseline: 3.7966x; 1.1998x over previous
#include <cuda_runtime.h>
#include <cstdint>
#include <math.h>

#define B_  2
#define S_  2048
#define E_  2048
#define H_  16
#define D_  128
#define E3_ 6144

// ---------------- scratch ----------------
__device__ float g_qkv[B_ * S_ * E3_];
__device__ float g_xr [B_ * S_ * E_];      // tf32, K-interleaved cols
__device__ float g_wqkvT[E3_ * E_];        // [3E,E] tf32, K-interleaved cols
__device__ float g_woT [E_ * E_];          // [E,E]  tf32, K-interleaved cols
__device__ float g_q[B_ * H_ * S_ * D_];   // d-interleaved, tf32, scaled
__device__ float g_k[B_ * H_ * S_ * D_];   // d-interleaved, tf32
__device__ float g_v[B_ * H_ * S_ * D_];   // natural, tf32
__device__ float g_ao[B_ * S_ * E_];       // tf32, K-interleaved cols

// ---------------- helpers ----------------
__device__ __forceinline__ uint32_t smem_u32(const void* p) {
    uint32_t a;
    asm("{ .reg .u64 t; cvta.to.shared.u64 t, %1; cvt.u32.u64 %0, t; }" : "=r"(a) : "l"(p));
    return a;
}
__device__ __forceinline__ float tf32_rn(float x) {
    uint32_t u;
    asm("cvt.rna.tf32.f32 %0, %1;" : "=r"(u) : "f"(x));
    return __uint_as_float(u);
}

#define CP_ASYNC16(sa, gp) \
    asm volatile("cp.async.cg.shared.global [%0], [%1], 16;" :: "r"(sa), "l"(gp))
#define CP_COMMIT() asm volatile("cp.async.commit_group;" ::: "memory")
#define CP_WAIT1()  asm volatile("cp.async.wait_group 1;" ::: "memory")
#define CP_WAIT0()  asm volatile("cp.async.wait_group 0;" ::: "memory")

__device__ __forceinline__ void mma_tf32_16n8k8(
    float& c0, float& c1, float& c2, float& c3,
    uint32_t a0, uint32_t a1, uint32_t a2, uint32_t a3,
    uint32_t b0, uint32_t b1)
{
    asm volatile(
        "mma.sync.aligned.m16n8k8.row.col.f32.tf32.tf32.f32 "
        "{%0,%1,%2,%3}, {%4,%5,%6,%7}, {%8,%9}, {%0,%1,%2,%3};"
        : "+f"(c0), "+f"(c1), "+f"(c2), "+f"(c3)
        : "r"(a0), "r"(a1), "r"(a2), "r"(a3), "r"(b0), "r"(b1));
}

// ============================================================================
// tf32 mma.sync GEMM v2: C[M,Ntot] = A[M,K] @ Bt[Ntot,K]^T
// A/Bt have K-INTERLEAVED columns (within each 8-block, orig k stored at
// ((k&3)<<1)|((k>>2)&1)).  Smem: 32 floats/row (128B), XOR-swizzled chunks
// (chunk c of row r stored at c ^ (2*(r&3))). LDS.64 fragments, conflict-free.
// 128x128 block, BK=32, 8 warps (64x32 warp tile), 3-stage cp.async pipeline,
// 2 CTAs/SM.
// ============================================================================
#define GSZ 4096                       // floats per operand per stage (128*32)
#define GEMM_SMEM (3 * 2 * GSZ * 4)    // 98304 B

__global__ __launch_bounds__(256, 2) void gemm_mma(
    const float* __restrict__ A, const float* __restrict__ Bt,
    float* __restrict__ C, int M, int Ntot, int K)
{
    extern __shared__ float sm[];
    const int tid  = threadIdx.x;
    const int wid  = tid >> 5;
    const int lane = tid & 31;
    const int gid  = lane >> 2;
    const int tig  = lane & 3;
    const int wm   = wid & 1;
    const int wn   = wid >> 1;
    const int m0 = blockIdx.y * 128;
    const int n0 = blockIdx.x * 128;

    // cp.async mapping: 256 threads cover 32 rows x 8 chunks per iteration
    const int r_ld = tid >> 3;                    // 0..31
    const int c_ld = tid & 7;
    const int c_sw = c_ld ^ ((r_ld & 3) << 1);    // swizzled store chunk

    // fragment addressing constants
    const int x = (gid & 3) << 1;                       // read-side chunk xor
    const int fragoff = ((tig >> 1) << 2) + ((tig & 1) << 1);  // floats

    float c[4][4][4];
#pragma unroll
    for (int i = 0; i < 4; ++i)
#pragma unroll
        for (int j = 0; j < 4; ++j)
#pragma unroll
            for (int t = 0; t < 4; ++t) c[i][j][t] = 0.f;

    auto load_stage = [&](int kc, int slot) {
        float* As = sm + slot * 2 * GSZ;
        float* Bs = As + GSZ;
        const float* Ag = A + (size_t)m0 * K + kc * 32;
        const float* Bg = Bt + (size_t)n0 * K + kc * 32;
#pragma unroll
        for (int j = 0; j < 4; ++j) {
            int r = r_ld + j * 32;
            CP_ASYNC16(smem_u32(As + r * 32 + c_sw * 4), Ag + (size_t)r * K + c_ld * 4);
        }
#pragma unroll
        for (int j = 0; j < 4; ++j) {
            int r = r_ld + j * 32;
            CP_ASYNC16(smem_u32(Bs + r * 32 + c_sw * 4), Bg + (size_t)r * K + c_ld * 4);
        }
    };

    const int nk = K >> 5;
    load_stage(0, 0); CP_COMMIT();
    load_stage(1, 1); CP_COMMIT();

    for (int kc = 0; kc < nk; ++kc) {
        CP_WAIT1();
        __syncthreads();
        if (kc + 2 < nk) { load_stage(kc + 2, (kc + 2) % 3); CP_COMMIT(); }

        const float* As = sm + (kc % 3) * 2 * GSZ;
        const float* Bs = As + GSZ;
        const float* Aw = As + (wm * 64 + gid) * 32;  // + mt*512, +256 for row+8
        const float* Bw = Bs + (wn * 32 + gid) * 32;  // + nt*256

#pragma unroll
        for (int ks = 0; ks < 4; ++ks) {
            const int koff = (((ks << 1) ^ x) << 2) + fragoff;
            uint32_t a[4][4], b[4][2];
#pragma unroll
            for (int mt = 0; mt < 4; ++mt) {
                float2 p0 = *(const float2*)(Aw + mt * 512 + koff);
                float2 p1 = *(const float2*)(Aw + mt * 512 + 256 + koff);
                a[mt][0] = __float_as_uint(p0.x);
                a[mt][1] = __float_as_uint(p1.x);
                a[mt][2] = __float_as_uint(p0.y);
                a[mt][3] = __float_as_uint(p1.y);
            }
#pragma unroll
            for (int nt = 0; nt < 4; ++nt) {
                float2 pb = *(const float2*)(Bw + nt * 256 + koff);
                b[nt][0] = __float_as_uint(pb.x);
                b[nt][1] = __float_as_uint(pb.y);
            }
#pragma unroll
            for (int mt = 0; mt < 4; ++mt)
#pragma unroll
                for (int nt = 0; nt < 4; ++nt)
                    mma_tf32_16n8k8(c[mt][nt][0], c[mt][nt][1], c[mt][nt][2], c[mt][nt][3],
                                    a[mt][0], a[mt][1], a[mt][2], a[mt][3],
                                    b[nt][0], b[nt][1]);
        }
        __syncthreads();
    }

    // epilogue (output natural layout)
#pragma unroll
    for (int mt = 0; mt < 4; ++mt) {
        int r0 = m0 + wm * 64 + mt * 16 + gid;
#pragma unroll
        for (int nt = 0; nt < 4; ++nt) {
            int col = n0 + wn * 32 + nt * 8 + 2 * tig;
            *(float2*)(C + (size_t)r0 * Ntot + col) = make_float2(c[mt][nt][0], c[mt][nt][1]);
            *(float2*)(C + (size_t)(r0 + 8) * Ntot + col) = make_float2(c[mt][nt][2], c[mt][nt][3]);
        }
    }
}

// ============================================================================
// prep kernels (K-interleave + tf32 round)
// interleave within each 8-block: out[2t]=in[t], out[2t+1]=in[t+4]  (zip)
// ============================================================================
__global__ __launch_bounds__(256) void round_copy(const float* __restrict__ in,
                                                  float* __restrict__ out) {
    int i = blockIdx.x * 256 + threadIdx.x;   // one 8-float block per thread
    const float4* p = (const float4*)(in) + 2 * i;
    float4 lo = p[0], hi = p[1];
    float4 o0 = make_float4(tf32_rn(lo.x), tf32_rn(hi.x), tf32_rn(lo.y), tf32_rn(hi.y));
    float4 o1 = make_float4(tf32_rn(lo.z), tf32_rn(hi.z), tf32_rn(lo.w), tf32_rn(hi.w));
    float4* q = (float4*)(out) + 2 * i;
    q[0] = o0; q[1] = o1;
}

// W[K][N] -> Wt[N][K], tf32-rounded, K-interleaved columns
__global__ __launch_bounds__(256) void transpose_round(
    const float* __restrict__ W, float* __restrict__ Wt, int K, int N)
{
    __shared__ float t[32][33];
    int n0 = blockIdx.x * 32, k0 = blockIdx.y * 32;
    int tx = threadIdx.x & 31, ty = threadIdx.x >> 5;
#pragma unroll
    for (int j = 0; j < 4; ++j)
        t[ty + j * 8][tx] = W[(size_t)(k0 + ty + j * 8) * N + n0 + tx];
    __syncthreads();
    int ktx = (tx & 24) | (((tx & 3) << 1) | ((tx >> 2) & 1));
#pragma unroll
    for (int j = 0; j < 4; ++j)
        Wt[(size_t)(n0 + ty + j * 8) * K + k0 + ktx] = tf32_rn(t[tx][ty + j * 8]);
}

// ============================================================================
// RoPE + scatter (unchanged from R6 — validated)
// ============================================================================
__global__ __launch_bounds__(256) void rope_scatter(
    const float* __restrict__ qkv, const float* __restrict__ fc,
    float* __restrict__ Q, float* __restrict__ K, float* __restrict__ V)
{
    int idx = blockIdx.x * blockDim.x + threadIdx.x;
    int i = idx & 63;
    int h = (idx >> 6) & 15;
    int s = (idx >> 10) & 2047;
    int b = idx >> 21;

    const float* row = qkv + (size_t)(b * S_ + s) * E3_;
    float2 q = *(const float2*)(row + h * D_ + 2 * i);
    float2 k = *(const float2*)(row + E_ + h * D_ + 2 * i);
    float2 v = *(const float2*)(row + 2 * E_ + h * D_ + 2 * i);

    float c = fc[s * 128 + 2 * i];
    float sn = fc[s * 128 + 2 * i + 1];
    const float sc = 0.08838834764831845f;  // 1/sqrt(128)

    float q0v = tf32_rn((q.x * c - q.y * sn) * sc);
    float q1v = tf32_rn((q.y * c + q.x * sn) * sc);
    float k0v = tf32_rn(k.x * c - k.y * sn);
    float k1v = tf32_rn(k.y * c + k.x * sn);

    int d0 = 2 * i, d1 = 2 * i + 1;
    int p0 = (d0 & ~7) | (((d0 & 3) << 1) | ((d0 >> 2) & 1));
    int p1 = (d1 & ~7) | (((d1 & 3) << 1) | ((d1 >> 2) & 1));

    size_t o = ((size_t)((b * H_ + h) * S_) + s) * D_;
    Q[o + p0] = q0v; Q[o + p1] = q1v;
    K[o + p0] = k0v; K[o + p1] = k1v;
    *(float2*)(V + o + d0) = make_float2(tf32_rn(v.x), tf32_rn(v.y));
}

// ============================================================================
// Flash attention (R6-validated; epilogue now writes K-interleaved AO cols)
// ============================================================================
#define KSP 136
#define VSP 72
#define PSP 72
#define KS_F (64 * KSP)
#define VTS_F (128 * VSP)
#define PS_F (128 * PSP)
#define FL_SMEM ((2 * KS_F + 2 * VTS_F + PS_F) * 4)

__global__ __launch_bounds__(256, 1) void flash_mma(
    const float* __restrict__ Qg, const float* __restrict__ Kg,
    const float* __restrict__ Vg, float* __restrict__ Og)
{
    extern __shared__ float sm[];
    float* Ks  = sm;                 // [2][64][KSP]
    float* Vts = sm + 2 * KS_F;      // [2][128][VSP]
    float* Ps  = Vts + 2 * VTS_F;    // [128][PSP]

    const int tid  = threadIdx.x;
    const int wid  = tid >> 5;
    const int lane = tid & 31;
    const int gid  = lane >> 2;
    const int tig  = lane & 3;
    const int b = blockIdx.z, h = blockIdx.y;
    const int qt = (int)gridDim.x - 1 - (int)blockIdx.x;
    const int q0 = qt * 128;
    const int wrow = wid * 16;
    const size_t base = (size_t)(b * H_ + h) * S_ * D_;

    float2 aq[16][2];
    {
        const float* Qp0 = Qg + base + (size_t)(q0 + wrow + gid) * D_ + 2 * tig;
        const float* Qp1 = Qp0 + 8 * D_;
#pragma unroll
        for (int ks = 0; ks < 16; ++ks) {
            aq[ks][0] = *(const float2*)(Qp0 + 8 * ks);
            aq[ks][1] = *(const float2*)(Qp1 + 8 * ks);
        }
    }

    float accO[16][4];
#pragma unroll
    for (int nt = 0; nt < 16; ++nt)
#pragma unroll
        for (int t = 0; t < 4; ++t) accO[nt][t] = 0.f;
    float mrow[2] = {-3.0e38f, -3.0e38f};
    float lrow[2] = {0.f, 0.f};

    auto load_K = [&](int kt, int bf) {
        const float* Kgp = Kg + base + (size_t)kt * 64 * D_;
        float* dst = Ks + bf * KS_F;
#pragma unroll
        for (int j = 0; j < 8; ++j) {
            int q = tid + j * 256;
            int r = q >> 5, cc = q & 31;
            CP_ASYNC16(smem_u32(dst + r * KSP + cc * 4), Kgp + (size_t)r * D_ + cc * 4);
        }
    };
    auto load_V = [&](int kt, int bf) {
        const float* Vgp = Vg + base + (size_t)kt * 64 * D_;
        float* dst = Vts + bf * VTS_F;
#pragma unroll
        for (int j = 0; j < 8; ++j) {
            int e = tid + j * 256;
            int key = e & 63, d4 = e >> 6;
            float4 v = *(const float4*)(Vgp + (size_t)key * D_ + d4 * 4);
            int ik = (key & ~7) | (((key & 3) << 1) | ((key >> 2) & 1));
            dst[(d4 * 4 + 0) * VSP + ik] = v.x;
            dst[(d4 * 4 + 1) * VSP + ik] = v.y;
            dst[(d4 * 4 + 2) * VSP + ik] = v.z;
            dst[(d4 * 4 + 3) * VSP + ik] = v.w;
        }
    };

    const int nkt = 2 * qt + 1;
    load_K(0, 0); CP_COMMIT();
    load_V(0, 0);

    const int row0s = (wrow + gid) * PSP;
    const int row1s = row0s + 8 * PSP;
    const int c0i = 2 * tig, c1i = 2 * tig + 1;
    const int j0 = ((c0i & 3) << 1) | ((c0i >> 2) & 1);
    const int j1 = ((c1i & 3) << 1) | ((c1i >> 2) & 1);

    for (int kt = 0; kt <= nkt; ++kt) {
        const int cur = kt & 1, nxt = cur ^ 1;
        if (kt < nkt) { load_K(kt + 1, nxt); CP_COMMIT(); CP_WAIT1(); }
        else         { CP_WAIT0(); }
        __syncthreads();

        float sacc[8][4];
#pragma unroll
        for (int nt = 0; nt < 8; ++nt)
#pragma unroll
            for (int t = 0; t < 4; ++t) sacc[nt][t] = 0.f;

        const float* Kb = Ks + cur * KS_F + gid * KSP + 2 * tig;
#pragma unroll
        for (int ks = 0; ks < 16; ++ks) {
            uint32_t a0 = __float_as_uint(aq[ks][0].x);
            uint32_t a1 = __float_as_uint(aq[ks][1].x);
            uint32_t a2 = __float_as_uint(aq[ks][0].y);
            uint32_t a3 = __float_as_uint(aq[ks][1].y);
#pragma unroll
            for (int nt = 0; nt < 8; ++nt) {
                float2 bb = *(const float2*)(Kb + nt * 8 * KSP + ks * 8);
                mma_tf32_16n8k8(sacc[nt][0], sacc[nt][1], sacc[nt][2], sacc[nt][3],
                                a0, a1, a2, a3,
                                __float_as_uint(bb.x), __float_as_uint(bb.y));
            }
        }

        if (kt < nkt) load_V(kt + 1, nxt);

        const int k0 = kt * 64;
        if (k0 + 63 > q0 + wrow) {
            int r0 = q0 + wrow + gid, r1 = r0 + 8;
#pragma unroll
            for (int nt = 0; nt < 8; ++nt) {
                int cA = k0 + nt * 8 + 2 * tig, cB = cA + 1;
                if (cA > r0) sacc[nt][0] = -1.0e30f;
                if (cB > r0) sacc[nt][1] = -1.0e30f;
                if (cA > r1) sacc[nt][2] = -1.0e30f;
                if (cB > r1) sacc[nt][3] = -1.0e30f;
            }
        }

        float mx0 = -3.0e38f, mx1 = -3.0e38f;
#pragma unroll
        for (int nt = 0; nt < 8; ++nt) {
            mx0 = fmaxf(mx0, fmaxf(sacc[nt][0], sacc[nt][1]));
            mx1 = fmaxf(mx1, fmaxf(sacc[nt][2], sacc[nt][3]));
        }
        mx0 = fmaxf(mx0, __shfl_xor_sync(0xffffffffu, mx0, 1));
        mx0 = fmaxf(mx0, __shfl_xor_sync(0xffffffffu, mx0, 2));
        mx1 = fmaxf(mx1, __shfl_xor_sync(0xffffffffu, mx1, 1));
        mx1 = fmaxf(mx1, __shfl_xor_sync(0xffffffffu, mx1, 2));

        float mn0 = fmaxf(mrow[0], mx0);
        float mn1 = fmaxf(mrow[1], mx1);
        float al0 = __expf(mrow[0] - mn0);
        float al1 = __expf(mrow[1] - mn1);
        mrow[0] = mn0; mrow[1] = mn1;

        float s0 = 0.f, s1 = 0.f;
#pragma unroll
        for (int nt = 0; nt < 8; ++nt) {
            sacc[nt][0] = __expf(sacc[nt][0] - mn0);
            sacc[nt][1] = __expf(sacc[nt][1] - mn0);
            sacc[nt][2] = __expf(sacc[nt][2] - mn1);
            sacc[nt][3] = __expf(sacc[nt][3] - mn1);
            s0 += sacc[nt][0] + sacc[nt][1];
            s1 += sacc[nt][2] + sacc[nt][3];
        }
        s0 += __shfl_xor_sync(0xffffffffu, s0, 1);
        s0 += __shfl_xor_sync(0xffffffffu, s0, 2);
        s1 += __shfl_xor_sync(0xffffffffu, s1, 1);
        s1 += __shfl_xor_sync(0xffffffffu, s1, 2);
        lrow[0] = lrow[0] * al0 + s0;
        lrow[1] = lrow[1] * al1 + s1;

#pragma unroll
        for (int nt = 0; nt < 16; ++nt) {
            accO[nt][0] *= al0; accO[nt][1] *= al0;
            accO[nt][2] *= al1; accO[nt][3] *= al1;
        }
#pragma unroll
        for (int nt = 0; nt < 8; ++nt) {
            int bb = nt * 8;
            Ps[row0s + bb + j0] = tf32_rn(sacc[nt][0]);
            Ps[row0s + bb + j1] = tf32_rn(sacc[nt][1]);
            Ps[row1s + bb + j0] = tf32_rn(sacc[nt][2]);
            Ps[row1s + bb + j1] = tf32_rn(sacc[nt][3]);
        }
        __syncthreads();

        const float* Vb = Vts + cur * VTS_F + gid * VSP + 2 * tig;
#pragma unroll
        for (int ks2 = 0; ks2 < 8; ++ks2) {
            float2 pa0 = *(const float2*)(Ps + row0s + ks2 * 8 + 2 * tig);
            float2 pa1 = *(const float2*)(Ps + row1s + ks2 * 8 + 2 * tig);
            uint32_t a0 = __float_as_uint(pa0.x);
            uint32_t a1 = __float_as_uint(pa1.x);
            uint32_t a2 = __float_as_uint(pa0.y);
            uint32_t a3 = __float_as_uint(pa1.y);
#pragma unroll
            for (int nt = 0; nt < 16; ++nt) {
                float2 vb = *(const float2*)(Vb + nt * 8 * VSP + ks2 * 8);
                mma_tf32_16n8k8(accO[nt][0], accO[nt][1], accO[nt][2], accO[nt][3],
                                a0, a1, a2, a3,
                                __float_as_uint(vb.x), __float_as_uint(vb.y));
            }
        }
    }

    // ---- epilogue: AO written with K-interleaved columns (GEMM2 input) ----
    float inv0 = 1.f / lrow[0];
    float inv1 = 1.f / lrow[1];
    int qrow = q0 + wrow + gid;
    float* O0 = Og + (size_t)(b * S_ + qrow) * E_ + h * D_;
    float* O1 = O0 + 8 * (size_t)E_;
#pragma unroll
    for (int nt = 0; nt < 16; ++nt) {
        int cb = nt * 8;
        O0[cb + j0] = tf32_rn(accO[nt][0] * inv0);
        O0[cb + j1] = tf32_rn(accO[nt][1] * inv0);
        O1[cb + j0] = tf32_rn(accO[nt][2] * inv1);
        O1[cb + j1] = tf32_rn(accO[nt][3] * inv1);
    }
}

// ============================================================================
// kernel_launch
// ============================================================================
extern "C" void kernel_launch(void* const* d_in, const int* in_sizes, int n_in,
                              void* d_out, int out_size)
{
    const float* x    = (const float*)d_in[0];
    const float* Wqkv = (const float*)d_in[1];
    const float* Wo   = (const float*)d_in[2];
    const float* fc   = (const float*)d_in[3];
    float* out = (float*)d_out;

    float *qkv, *xr, *wqkvT, *woT, *Q, *K, *V, *AO;
    cudaGetSymbolAddress((void**)&qkv, g_qkv);
    cudaGetSymbolAddress((void**)&xr, g_xr);
    cudaGetSymbolAddress((void**)&wqkvT, g_wqkvT);
    cudaGetSymbolAddress((void**)&woT, g_woT);
    cudaGetSymbolAddress((void**)&Q, g_q);
    cudaGetSymbolAddress((void**)&K, g_k);
    cudaGetSymbolAddress((void**)&V, g_v);
    cudaGetSymbolAddress((void**)&AO, g_ao);

    cudaFuncSetAttribute(gemm_mma, cudaFuncAttributeMaxDynamicSharedMemorySize, GEMM_SMEM);
    cudaFuncSetAttribute(flash_mma, cudaFuncAttributeMaxDynamicSharedMemorySize, FL_SMEM);

    round_copy<<<(B_ * S_ * E_) / 8 / 256, 256>>>(x, xr);
    {
        dim3 g(E3_ / 32, E_ / 32);
        transpose_round<<<g, 256>>>(Wqkv, wqkvT, E_, E3_);
    }
    {
        dim3 g(E_ / 32, E_ / 32);
        transpose_round<<<g, 256>>>(Wo, woT, E_, E_);
    }

    // 1) QKV = xr @ WqkvT^T
    {
        dim3 grid(E3_ / 128, (B_ * S_) / 128);
        gemm_mma<<<grid, 256, GEMM_SMEM>>>(xr, wqkvT, qkv, B_ * S_, E3_, E_);
    }
    // 2) RoPE + scatter
    {
        int total = B_ * S_ * H_ * (D_ / 2);
        rope_scatter<<<total / 256, 256>>>(qkv, fc, Q, K, V);
    }
    // 3) flash attention
    {
        dim3 grid(S_ / 128, H_, B_);
        flash_mma<<<grid, 256, FL_SMEM>>>(Q, K, V, AO);
    }
    // 4) out = AO @ WoT^T
    {
        dim3 grid(E_ / 128, (B_ * S_) / 128);
        gemm_mma<<<grid, 256, GEMM_SMEM>>>(AO, woT, out, B_ * S_, E_, E_);
    }
}

// round 9
// speedup vs baseline: 5.6305x; 1.4830x over previous
#include <cuda_runtime.h>
#include <cuda_fp16.h>
#include <cstdint>
#include <math.h>

#define B_  2
#define S_  2048
#define E_  2048
#define H_  16
#define D_  128
#define E3_ 6144

// ---------------- scratch ----------------
__device__ float  g_qkv[B_ * S_ * E3_];      // QKV GEMM out, fp32
__device__ __half g_xh [B_ * S_ * E_];       // x, fp16, K-pair-interleaved
__device__ __half g_wqkvT[E3_ * E_];         // Wqkv^T fp16 interleaved
__device__ __half g_woT [E_ * E_];           // Wo^T fp16 interleaved
__device__ __half g_qh[B_ * H_ * S_ * D_];   // Q fp16 d-interleaved, scaled
__device__ __half g_kh[B_ * H_ * S_ * D_];   // K fp16 d-interleaved
__device__ __half g_vh[B_ * H_ * S_ * D_];   // V fp16 natural
__device__ __half g_aoh[B_ * S_ * E_];       // attn out fp16 interleaved

// ---------------- helpers ----------------
__device__ __forceinline__ uint32_t smem_u32(const void* p) {
    uint32_t a;
    asm("{ .reg .u64 t; cvta.to.shared.u64 t, %1; cvt.u32.u64 %0, t; }" : "=r"(a) : "l"(p));
    return a;
}

#define CP_ASYNC16(sa, gp) \
    asm volatile("cp.async.cg.shared.global [%0], [%1], 16;" :: "r"(sa), "l"(gp))
#define CP_COMMIT() asm volatile("cp.async.commit_group;" ::: "memory")
#define CP_WAIT1()  asm volatile("cp.async.wait_group 1;" ::: "memory")
#define CP_WAIT0()  asm volatile("cp.async.wait_group 0;" ::: "memory")

__device__ __forceinline__ void mma_f16_16n8k16(
    float& c0, float& c1, float& c2, float& c3,
    uint32_t a0, uint32_t a1, uint32_t a2, uint32_t a3,
    uint32_t b0, uint32_t b1)
{
    asm volatile(
        "mma.sync.aligned.m16n8k16.row.col.f32.f16.f16.f32 "
        "{%0,%1,%2,%3}, {%4,%5,%6,%7}, {%8,%9}, {%0,%1,%2,%3};"
        : "+f"(c0), "+f"(c1), "+f"(c2), "+f"(c3)
        : "r"(a0), "r"(a1), "r"(a2), "r"(a3), "r"(b0), "r"(b1));
}

// pair-interleave position: within each 16-half block, half t moves to
// newpos = np(pair)*2 + (t&1), np(p) = ((p&3)<<1)|((p>>2)&1)
__device__ __forceinline__ int ilv16(int t) {
    int p = (t >> 1) & 7;
    int np = ((p & 3) << 1) | ((p >> 2) & 1);
    return (t & ~15) | (np << 1) | (t & 1);
}

// ============================================================================
// fp16 mma.sync GEMM: C[M,Ntot](fp32) = A[M,K] @ Bt[Ntot,K]^T, A/Bt fp16 with
// K-pair-interleaved columns. Block 128x128, BK=64 (4 x k16), 8 warps
// (64x32 warp tile), 3-stage cp.async, 2 CTAs/SM. Smem rows 128B, chunk
// swizzle c ^ ((r&3)<<1).
// ============================================================================
#define GSZ 8192                        // halves per operand per stage (128*64)
#define GEMM_SMEM (3 * 2 * GSZ * 2)     // 98304 B

__global__ __launch_bounds__(256, 2) void gemm_mma(
    const __half* __restrict__ A, const __half* __restrict__ Bt,
    float* __restrict__ C, int M, int Ntot, int K)
{
    extern __shared__ __half smh[];
    const int tid  = threadIdx.x;
    const int wid  = tid >> 5;
    const int lane = tid & 31;
    const int gid  = lane >> 2;
    const int tig  = lane & 3;
    const int wm   = wid & 1;
    const int wn   = wid >> 1;
    const int m0 = blockIdx.y * 128;
    const int n0 = blockIdx.x * 128;

    const int r_ld = tid >> 3;                    // 0..31
    const int c_ld = tid & 7;                     // 16B chunk
    const int c_sw = c_ld ^ ((r_ld & 3) << 1);

    const int x = (gid & 3) << 1;                 // read-side chunk xor

    float c[4][4][4];
#pragma unroll
    for (int i = 0; i < 4; ++i)
#pragma unroll
        for (int j = 0; j < 4; ++j)
#pragma unroll
            for (int t = 0; t < 4; ++t) c[i][j][t] = 0.f;

    auto load_stage = [&](int kc, int slot) {
        __half* As = smh + slot * 2 * GSZ;
        __half* Bs = As + GSZ;
        const __half* Ag = A + (size_t)m0 * K + kc * 64;
        const __half* Bg = Bt + (size_t)n0 * K + kc * 64;
#pragma unroll
        for (int j = 0; j < 4; ++j) {
            int r = r_ld + j * 32;
            CP_ASYNC16(smem_u32(As + r * 64 + c_sw * 8), Ag + (size_t)r * K + c_ld * 8);
        }
#pragma unroll
        for (int j = 0; j < 4; ++j) {
            int r = r_ld + j * 32;
            CP_ASYNC16(smem_u32(Bs + r * 64 + c_sw * 8), Bg + (size_t)r * K + c_ld * 8);
        }
    };

    const int nk = K >> 6;
    load_stage(0, 0); CP_COMMIT();
    load_stage(1, 1); CP_COMMIT();

    for (int kc = 0; kc < nk; ++kc) {
        CP_WAIT1();
        __syncthreads();
        if (kc + 2 < nk) { load_stage(kc + 2, (kc + 2) % 3); CP_COMMIT(); }

        const __half* As = smh + (kc % 3) * 2 * GSZ;
        const __half* Bs = As + GSZ;
        const __half* Aw = As + (wm * 64 + gid) * 64;
        const __half* Bw = Bs + (wn * 32 + gid) * 64;

#pragma unroll
        for (int ks = 0; ks < 4; ++ks) {
            const int swc = (2 * ks + (tig >> 1)) ^ x;
            const int off = swc * 8 + (tig & 1) * 4;   // halves
            uint32_t a[4][4], b[4][2];
#pragma unroll
            for (int mt = 0; mt < 4; ++mt) {
                uint2 p0 = *(const uint2*)(Aw + mt * 1024 + off);
                uint2 p1 = *(const uint2*)(Aw + mt * 1024 + 512 + off);
                a[mt][0] = p0.x;  a[mt][2] = p0.y;
                a[mt][1] = p1.x;  a[mt][3] = p1.y;
            }
#pragma unroll
            for (int nt = 0; nt < 4; ++nt) {
                uint2 pb = *(const uint2*)(Bw + nt * 512 + off);
                b[nt][0] = pb.x;  b[nt][1] = pb.y;
            }
#pragma unroll
            for (int mt = 0; mt < 4; ++mt)
#pragma unroll
                for (int nt = 0; nt < 4; ++nt)
                    mma_f16_16n8k16(c[mt][nt][0], c[mt][nt][1], c[mt][nt][2], c[mt][nt][3],
                                    a[mt][0], a[mt][1], a[mt][2], a[mt][3],
                                    b[nt][0], b[nt][1]);
        }
        __syncthreads();
    }

#pragma unroll
    for (int mt = 0; mt < 4; ++mt) {
        int r0 = m0 + wm * 64 + mt * 16 + gid;
#pragma unroll
        for (int nt = 0; nt < 4; ++nt) {
            int col = n0 + wn * 32 + nt * 8 + 2 * tig;
            *(float2*)(C + (size_t)r0 * Ntot + col) = make_float2(c[mt][nt][0], c[mt][nt][1]);
            *(float2*)(C + (size_t)(r0 + 8) * Ntot + col) = make_float2(c[mt][nt][2], c[mt][nt][3]);
        }
    }
}

// ============================================================================
// prep: fp32 -> fp16 with K-pair-interleave (one 16-elem block per thread)
// ============================================================================
__global__ __launch_bounds__(256) void round_copy_h(const float* __restrict__ in,
                                                    __half* __restrict__ out) {
    int i = blockIdx.x * 256 + threadIdx.x;
    const float* p = in + 16 * i;
    __half2 h[8];
#pragma unroll
    for (int j = 0; j < 8; ++j) {
        int pp = (j >> 1) | ((j & 1) << 2);   // inverse of np
        h[j] = __floats2half2_rn(p[2 * pp], p[2 * pp + 1]);
    }
    uint4* q = (uint4*)(out + 16 * i);
    q[0] = *(uint4*)(h);
    q[1] = *(uint4*)(h + 4);
}

// W[K][N] -> Wt[N][K] fp16, K-pair-interleaved
__global__ __launch_bounds__(256) void transpose_round_h(
    const float* __restrict__ W, __half* __restrict__ Wt, int K, int N)
{
    __shared__ float t[32][33];
    int n0 = blockIdx.x * 32, k0 = blockIdx.y * 32;
    int tx = threadIdx.x & 31, ty = threadIdx.x >> 5;
#pragma unroll
    for (int j = 0; j < 4; ++j)
        t[ty + j * 8][tx] = W[(size_t)(k0 + ty + j * 8) * N + n0 + tx];
    __syncthreads();
    int ktx = ilv16(tx);
#pragma unroll
    for (int j = 0; j < 4; ++j)
        Wt[(size_t)(n0 + ty + j * 8) * K + k0 + ktx] = __float2half(t[tx][ty + j * 8]);
}

// ============================================================================
// RoPE + scatter -> fp16. Q,K d-pair-interleaved (rotary pair == fp16 pair);
// V natural. 1/sqrt(D) folded into Q.
// ============================================================================
__global__ __launch_bounds__(256) void rope_scatter(
    const float* __restrict__ qkv, const float* __restrict__ fc,
    __half* __restrict__ Q, __half* __restrict__ K, __half* __restrict__ V)
{
    int idx = blockIdx.x * blockDim.x + threadIdx.x;
    int i = idx & 63;
    int h = (idx >> 6) & 15;
    int s = (idx >> 10) & 2047;
    int b = idx >> 21;

    const float* row = qkv + (size_t)(b * S_ + s) * E3_;
    float2 q = *(const float2*)(row + h * D_ + 2 * i);
    float2 k = *(const float2*)(row + E_ + h * D_ + 2 * i);
    float2 v = *(const float2*)(row + 2 * E_ + h * D_ + 2 * i);

    float c = fc[s * 128 + 2 * i];
    float sn = fc[s * 128 + 2 * i + 1];
    const float sc = 0.08838834764831845f;  // 1/sqrt(128)

    __half2 qo = __floats2half2_rn((q.x * c - q.y * sn) * sc, (q.y * c + q.x * sn) * sc);
    __half2 ko = __floats2half2_rn(k.x * c - k.y * sn, k.y * c + k.x * sn);

    // pair index i within its 16-half (8-pair) block
    int blk = i >> 3, p = i & 7;
    int np = ((p & 3) << 1) | ((p >> 2) & 1);
    int pos = blk * 16 + np * 2;

    size_t o = ((size_t)((b * H_ + h) * S_) + s) * D_;
    *(__half2*)(Q + o + pos) = qo;
    *(__half2*)(K + o + pos) = ko;
    *(__half2*)(V + o + 2 * i) = __floats2half2_rn(v.x, v.y);
}

// ============================================================================
// Flash attention fp16 mma. BM=128, BN=64, 8 warps. Q in registers; K via
// cp.async double-buffer; V transposed+key-interleaved; P fp16 in smem.
// ============================================================================
#define KSP 136
#define VSP 72
#define PSP 72
#define KS_H (64 * KSP)
#define VTS_H (128 * VSP)
#define PS_H (128 * PSP)
#define FL_SMEM ((2 * KS_H + 2 * VTS_H + PS_H) * 2)

__global__ __launch_bounds__(256, 1) void flash_mma(
    const __half* __restrict__ Qg, const __half* __restrict__ Kg,
    const __half* __restrict__ Vg, __half* __restrict__ Og)
{
    extern __shared__ __half smh[];
    __half* Ks  = smh;                 // [2][64][KSP]
    __half* Vts = smh + 2 * KS_H;      // [2][128][VSP]
    __half* Ps  = Vts + 2 * VTS_H;     // [128][PSP]

    const int tid  = threadIdx.x;
    const int wid  = tid >> 5;
    const int lane = tid & 31;
    const int gid  = lane >> 2;
    const int tig  = lane & 3;
    const int b = blockIdx.z, h = blockIdx.y;
    const int qt = (int)gridDim.x - 1 - (int)blockIdx.x;
    const int q0 = qt * 128;
    const int wrow = wid * 16;
    const size_t base = (size_t)(b * H_ + h) * S_ * D_;

    // Q fragments: per k16 block ks (8 of them): a0,a2 from row gid, a1,a3 row+8
    uint2 aq[8][2];
    {
        const __half* Qp0 = Qg + base + (size_t)(q0 + wrow + gid) * D_ + tig * 4;
        const __half* Qp1 = Qp0 + 8 * D_;
#pragma unroll
        for (int ks = 0; ks < 8; ++ks) {
            aq[ks][0] = *(const uint2*)(Qp0 + ks * 16);
            aq[ks][1] = *(const uint2*)(Qp1 + ks * 16);
        }
    }

    float accO[16][4];
#pragma unroll
    for (int nt = 0; nt < 16; ++nt)
#pragma unroll
        for (int t = 0; t < 4; ++t) accO[nt][t] = 0.f;
    float mrow[2] = {-3.0e38f, -3.0e38f};
    float lrow[2] = {0.f, 0.f};

    auto load_K = [&](int kt, int bf) {
        const __half* Kgp = Kg + base + (size_t)kt * 64 * D_;
        __half* dst = Ks + bf * KS_H;
#pragma unroll
        for (int j = 0; j < 4; ++j) {
            int q = tid + j * 256;
            int r = q >> 4, cc = q & 15;
            CP_ASYNC16(smem_u32(dst + r * KSP + cc * 8), Kgp + (size_t)r * D_ + cc * 8);
        }
    };
    auto load_V = [&](int kt, int bf) {
        const __half* Vgp = Vg + base + (size_t)kt * 64 * D_;
        __half* dst = Vts + bf * VTS_H;
#pragma unroll
        for (int j = 0; j < 8; ++j) {
            int e = tid + j * 256;             // 2048 x 4-half groups
            int key = e & 63, d4 = e >> 6;
            uint2 v4 = *(const uint2*)(Vgp + (size_t)key * D_ + d4 * 4);
            __half2 lo = *(__half2*)&v4.x;
            __half2 hi = *(__half2*)&v4.y;
            int ik = ilv16(key);               // key-pair interleave (16-key blocks)
            dst[(d4 * 4 + 0) * VSP + ik] = __low2half(lo);
            dst[(d4 * 4 + 1) * VSP + ik] = __high2half(lo);
            dst[(d4 * 4 + 2) * VSP + ik] = __low2half(hi);
            dst[(d4 * 4 + 3) * VSP + ik] = __high2half(hi);
        }
    };

    const int nkt = 2 * qt + 1;
    load_K(0, 0); CP_COMMIT();
    load_V(0, 0);

    const int row0s = (wrow + gid) * PSP;
    const int row1s = row0s + 8 * PSP;

    for (int kt = 0; kt <= nkt; ++kt) {
        const int cur = kt & 1, nxt = cur ^ 1;
        if (kt < nkt) { load_K(kt + 1, nxt); CP_COMMIT(); CP_WAIT1(); }
        else         { CP_WAIT0(); }
        __syncthreads();

        // ---- S = Q @ K^T ----
        float sacc[8][4];
#pragma unroll
        for (int nt = 0; nt < 8; ++nt)
#pragma unroll
            for (int t = 0; t < 4; ++t) sacc[nt][t] = 0.f;

        const __half* Kb = Ks + cur * KS_H + gid * KSP + tig * 4;
#pragma unroll
        for (int ks = 0; ks < 8; ++ks) {
#pragma unroll
            for (int nt = 0; nt < 8; ++nt) {
                uint2 bb = *(const uint2*)(Kb + nt * 8 * KSP + ks * 16);
                mma_f16_16n8k16(sacc[nt][0], sacc[nt][1], sacc[nt][2], sacc[nt][3],
                                aq[ks][0].x, aq[ks][1].x, aq[ks][0].y, aq[ks][1].y,
                                bb.x, bb.y);
            }
        }

        if (kt < nkt) load_V(kt + 1, nxt);

        // ---- causal mask ----
        const int k0 = kt * 64;
        if (k0 + 63 > q0 + wrow) {
            int r0 = q0 + wrow + gid, r1 = r0 + 8;
#pragma unroll
            for (int nt = 0; nt < 8; ++nt) {
                int cA = k0 + nt * 8 + 2 * tig, cB = cA + 1;
                if (cA > r0) sacc[nt][0] = -1.0e30f;
                if (cB > r0) sacc[nt][1] = -1.0e30f;
                if (cA > r1) sacc[nt][2] = -1.0e30f;
                if (cB > r1) sacc[nt][3] = -1.0e30f;
            }
        }

        // ---- online softmax ----
        float mx0 = -3.0e38f, mx1 = -3.0e38f;
#pragma unroll
        for (int nt = 0; nt < 8; ++nt) {
            mx0 = fmaxf(mx0, fmaxf(sacc[nt][0], sacc[nt][1]));
            mx1 = fmaxf(mx1, fmaxf(sacc[nt][2], sacc[nt][3]));
        }
        mx0 = fmaxf(mx0, __shfl_xor_sync(0xffffffffu, mx0, 1));
        mx0 = fmaxf(mx0, __shfl_xor_sync(0xffffffffu, mx0, 2));
        mx1 = fmaxf(mx1, __shfl_xor_sync(0xffffffffu, mx1, 1));
        mx1 = fmaxf(mx1, __shfl_xor_sync(0xffffffffu, mx1, 2));

        float mn0 = fmaxf(mrow[0], mx0);
        float mn1 = fmaxf(mrow[1], mx1);
        float al0 = __expf(mrow[0] - mn0);
        float al1 = __expf(mrow[1] - mn1);
        mrow[0] = mn0; mrow[1] = mn1;

        float s0 = 0.f, s1 = 0.f;
#pragma unroll
        for (int nt = 0; nt < 8; ++nt) {
            sacc[nt][0] = __expf(sacc[nt][0] - mn0);
            sacc[nt][1] = __expf(sacc[nt][1] - mn0);
            sacc[nt][2] = __expf(sacc[nt][2] - mn1);
            sacc[nt][3] = __expf(sacc[nt][3] - mn1);
            s0 += sacc[nt][0] + sacc[nt][1];
            s1 += sacc[nt][2] + sacc[nt][3];
        }
        s0 += __shfl_xor_sync(0xffffffffu, s0, 1);
        s0 += __shfl_xor_sync(0xffffffffu, s0, 2);
        s1 += __shfl_xor_sync(0xffffffffu, s1, 1);
        s1 += __shfl_xor_sync(0xffffffffu, s1, 2);
        lrow[0] = lrow[0] * al0 + s0;
        lrow[1] = lrow[1] * al1 + s1;

#pragma unroll
        for (int nt = 0; nt < 16; ++nt) {
            accO[nt][0] *= al0; accO[nt][1] *= al0;
            accO[nt][2] *= al1; accO[nt][3] *= al1;
        }
        // ---- P -> smem fp16, key-pair-interleaved within 16-key (16-half) blocks ----
#pragma unroll
        for (int nt = 0; nt < 8; ++nt) {
            int np = 2 * tig + (nt & 1);
            int off = (nt >> 1) * 16 + np * 2;   // FIX: 16-half block stride
            *(__half2*)(Ps + row0s + off) = __floats2half2_rn(sacc[nt][0], sacc[nt][1]);
            *(__half2*)(Ps + row1s + off) = __floats2half2_rn(sacc[nt][2], sacc[nt][3]);
        }
        __syncthreads();

        // ---- O += P @ V ----
        const __half* Vb = Vts + cur * VTS_H + gid * VSP + tig * 4;
        const __half* Pb0 = Ps + row0s + tig * 4;
        const __half* Pb1 = Ps + row1s + tig * 4;
#pragma unroll
        for (int ks2 = 0; ks2 < 4; ++ks2) {
            uint2 pa0 = *(const uint2*)(Pb0 + ks2 * 16);
            uint2 pa1 = *(const uint2*)(Pb1 + ks2 * 16);
#pragma unroll
            for (int nt = 0; nt < 16; ++nt) {
                uint2 vb = *(const uint2*)(Vb + nt * 8 * VSP + ks2 * 16);
                mma_f16_16n8k16(accO[nt][0], accO[nt][1], accO[nt][2], accO[nt][3],
                                pa0.x, pa1.x, pa0.y, pa1.y,
                                vb.x, vb.y);
            }
        }
    }

    // ---- epilogue: AO fp16, K-pair-interleaved columns (GEMM2 input) ----
    float inv0 = 1.f / lrow[0];
    float inv1 = 1.f / lrow[1];
    int qrow = q0 + wrow + gid;
    __half* O0 = Og + (size_t)(b * S_ + qrow) * E_ + h * D_;
    __half* O1 = O0 + 8 * (size_t)E_;
#pragma unroll
    for (int nt = 0; nt < 16; ++nt) {
        int np = 2 * tig + (nt & 1);
        int off = (nt >> 1) * 16 + np * 2;
        *(__half2*)(O0 + off) = __floats2half2_rn(accO[nt][0] * inv0, accO[nt][1] * inv0);
        *(__half2*)(O1 + off) = __floats2half2_rn(accO[nt][2] * inv1, accO[nt][3] * inv1);
    }
}

// ============================================================================
// kernel_launch
// ============================================================================
extern "C" void kernel_launch(void* const* d_in, const int* in_sizes, int n_in,
                              void* d_out, int out_size)
{
    const float* x    = (const float*)d_in[0];
    const float* Wqkv = (const float*)d_in[1];
    const float* Wo   = (const float*)d_in[2];
    const float* fc   = (const float*)d_in[3];
    float* out = (float*)d_out;

    float *qkv;
    __half *xh, *wqkvT, *woT, *Q, *K, *V, *AO;
    cudaGetSymbolAddress((void**)&qkv, g_qkv);
    cudaGetSymbolAddress((void**)&xh, g_xh);
    cudaGetSymbolAddress((void**)&wqkvT, g_wqkvT);
    cudaGetSymbolAddress((void**)&woT, g_woT);
    cudaGetSymbolAddress((void**)&Q, g_qh);
    cudaGetSymbolAddress((void**)&K, g_kh);
    cudaGetSymbolAddress((void**)&V, g_vh);
    cudaGetSymbolAddress((void**)&AO, g_aoh);

    cudaFuncSetAttribute(gemm_mma, cudaFuncAttributeMaxDynamicSharedMemorySize, GEMM_SMEM);
    cudaFuncSetAttribute(flash_mma, cudaFuncAttributeMaxDynamicSharedMemorySize, FL_SMEM);

    round_copy_h<<<(B_ * S_ * E_) / 16 / 256, 256>>>(x, xh);
    {
        dim3 g(E3_ / 32, E_ / 32);
        transpose_round_h<<<g, 256>>>(Wqkv, wqkvT, E_, E3_);
    }
    {
        dim3 g(E_ / 32, E_ / 32);
        transpose_round_h<<<g, 256>>>(Wo, woT, E_, E_);
    }

    // 1) QKV = xh @ wqkvT^T
    {
        dim3 grid(E3_ / 128, (B_ * S_) / 128);
        gemm_mma<<<grid, 256, GEMM_SMEM>>>(xh, wqkvT, qkv, B_ * S_, E3_, E_);
    }
    // 2) RoPE + scatter -> fp16
    {
        int total = B_ * S_ * H_ * (D_ / 2);
        rope_scatter<<<total / 256, 256>>>(qkv, fc, Q, K, V);
    }
    // 3) flash attention
    {
        dim3 grid(S_ / 128, H_, B_);
        flash_mma<<<grid, 256, FL_SMEM>>>(Q, K, V, AO);
    }
    // 4) out = AO @ woT^T
    {
        dim3 grid(E_ / 128, (B_ * S_) / 128);
        gemm_mma<<<grid, 256, GEMM_SMEM>>>(AO, woT, out, B_ * S_, E_, E_);
    }
}

// round 10
// speedup vs baseline: 5.7764x; 1.0259x over previous
#include <cuda_runtime.h>
#include <cuda_fp16.h>
#include <cstdint>
#include <math.h>

#define B_  2
#define S_  2048
#define E_  2048
#define H_  16
#define D_  128
#define E3_ 6144

// ---------------- scratch ----------------
__device__ __half g_xh [B_ * S_ * E_];       // x, fp16, K-pair-interleaved
__device__ __half g_wqkvT[E3_ * E_];         // Wqkv^T fp16 interleaved
__device__ __half g_woT [E_ * E_];           // Wo^T fp16 interleaved
__device__ __half g_qh[B_ * H_ * S_ * D_];   // Q fp16 d-interleaved, scaled
__device__ __half g_kh[B_ * H_ * S_ * D_];   // K fp16 d-interleaved
__device__ __half g_vh[B_ * H_ * S_ * D_];   // V fp16 natural
__device__ __half g_aoh[B_ * S_ * E_];       // attn out fp16 interleaved

// ---------------- helpers ----------------
__device__ __forceinline__ uint32_t smem_u32(const void* p) {
    uint32_t a;
    asm("{ .reg .u64 t; cvta.to.shared.u64 t, %1; cvt.u32.u64 %0, t; }" : "=r"(a) : "l"(p));
    return a;
}

#define CP_ASYNC16(sa, gp) \
    asm volatile("cp.async.cg.shared.global [%0], [%1], 16;" :: "r"(sa), "l"(gp))
#define CP_COMMIT() asm volatile("cp.async.commit_group;" ::: "memory")
#define CP_WAIT1()  asm volatile("cp.async.wait_group 1;" ::: "memory")
#define CP_WAIT0()  asm volatile("cp.async.wait_group 0;" ::: "memory")

__device__ __forceinline__ void mma_f16_16n8k16(
    float& c0, float& c1, float& c2, float& c3,
    uint32_t a0, uint32_t a1, uint32_t a2, uint32_t a3,
    uint32_t b0, uint32_t b1)
{
    asm volatile(
        "mma.sync.aligned.m16n8k16.row.col.f32.f16.f16.f32 "
        "{%0,%1,%2,%3}, {%4,%5,%6,%7}, {%8,%9}, {%0,%1,%2,%3};"
        : "+f"(c0), "+f"(c1), "+f"(c2), "+f"(c3)
        : "r"(a0), "r"(a1), "r"(a2), "r"(a3), "r"(b0), "r"(b1));
}

// pair-interleave position: within each 16-half block, half t moves to
// newpos = np(pair)*2 + (t&1), np(p) = ((p&3)<<1)|((p>>2)&1)
__device__ __forceinline__ int ilv16(int t) {
    int p = (t >> 1) & 7;
    int np = ((p & 3) << 1) | ((p >> 2) & 1);
    return (t & ~15) | (np << 1) | (t & 1);
}

// ============================================================================
// fp16 mma.sync GEMM with fused epilogue.
// mode 0: C fp32 natural (output projection).
// mode 1: QKV epilogue — RoPE applied in-register, Q/K/V written fp16 in the
//         flash layout (Q/K d-pair-interleaved, Q scaled; V natural).
// Block 128x128, BK=64, 8 warps (64x32 warp tile), 3-stage cp.async, 2 CTAs/SM.
// Single barrier per chunk (top-of-loop; 3-stage ring makes trailing sync
// redundant: slot loaded at chunk kc was last read in chunk kc-1, and the top
// barrier orders that).
// ============================================================================
#define GSZ 8192                        // halves per operand per stage (128*64)
#define GEMM_SMEM (3 * 2 * GSZ * 2)     // 98304 B

__global__ __launch_bounds__(256, 2) void gemm_mma(
    const __half* __restrict__ A, const __half* __restrict__ Bt,
    float* __restrict__ C, const float* __restrict__ fc,
    __half* __restrict__ Qo, __half* __restrict__ Ko, __half* __restrict__ Vo,
    int M, int Ntot, int K, int mode)
{
    extern __shared__ __half smh[];
    const int tid  = threadIdx.x;
    const int wid  = tid >> 5;
    const int lane = tid & 31;
    const int gid  = lane >> 2;
    const int tig  = lane & 3;
    const int wm   = wid & 1;
    const int wn   = wid >> 1;
    const int m0 = blockIdx.y * 128;
    const int n0 = blockIdx.x * 128;

    const int r_ld = tid >> 3;                    // 0..31
    const int c_ld = tid & 7;                     // 16B chunk
    const int c_sw = c_ld ^ ((r_ld & 3) << 1);

    const int x = (gid & 3) << 1;                 // read-side chunk xor

    float c[4][4][4];
#pragma unroll
    for (int i = 0; i < 4; ++i)
#pragma unroll
        for (int j = 0; j < 4; ++j)
#pragma unroll
            for (int t = 0; t < 4; ++t) c[i][j][t] = 0.f;

    auto load_stage = [&](int kc, int slot) {
        __half* As = smh + slot * 2 * GSZ;
        __half* Bs = As + GSZ;
        const __half* Ag = A + (size_t)m0 * K + kc * 64;
        const __half* Bg = Bt + (size_t)n0 * K + kc * 64;
#pragma unroll
        for (int j = 0; j < 4; ++j) {
            int r = r_ld + j * 32;
            CP_ASYNC16(smem_u32(As + r * 64 + c_sw * 8), Ag + (size_t)r * K + c_ld * 8);
        }
#pragma unroll
        for (int j = 0; j < 4; ++j) {
            int r = r_ld + j * 32;
            CP_ASYNC16(smem_u32(Bs + r * 64 + c_sw * 8), Bg + (size_t)r * K + c_ld * 8);
        }
    };

    const int nk = K >> 6;
    load_stage(0, 0); CP_COMMIT();
    load_stage(1, 1); CP_COMMIT();

    for (int kc = 0; kc < nk; ++kc) {
        CP_WAIT1();
        __syncthreads();
        if (kc + 2 < nk) { load_stage(kc + 2, (kc + 2) % 3); CP_COMMIT(); }

        const __half* As = smh + (kc % 3) * 2 * GSZ;
        const __half* Bs = As + GSZ;
        const __half* Aw = As + (wm * 64 + gid) * 64;
        const __half* Bw = Bs + (wn * 32 + gid) * 64;

#pragma unroll
        for (int ks = 0; ks < 4; ++ks) {
            const int swc = (2 * ks + (tig >> 1)) ^ x;
            const int off = swc * 8 + (tig & 1) * 4;   // halves
            uint32_t a[4][4], b[4][2];
#pragma unroll
            for (int mt = 0; mt < 4; ++mt) {
                uint2 p0 = *(const uint2*)(Aw + mt * 1024 + off);
                uint2 p1 = *(const uint2*)(Aw + mt * 1024 + 512 + off);
                a[mt][0] = p0.x;  a[mt][2] = p0.y;
                a[mt][1] = p1.x;  a[mt][3] = p1.y;
            }
#pragma unroll
            for (int nt = 0; nt < 4; ++nt) {
                uint2 pb = *(const uint2*)(Bw + nt * 512 + off);
                b[nt][0] = pb.x;  b[nt][1] = pb.y;
            }
#pragma unroll
            for (int mt = 0; mt < 4; ++mt)
#pragma unroll
                for (int nt = 0; nt < 4; ++nt)
                    mma_f16_16n8k16(c[mt][nt][0], c[mt][nt][1], c[mt][nt][2], c[mt][nt][3],
                                    a[mt][0], a[mt][1], a[mt][2], a[mt][3],
                                    b[nt][0], b[nt][1]);
        }
        // no trailing sync: top-of-loop barrier orders slot reuse (3-stage ring)
    }

    if (mode == 0) {
        // ---- plain fp32 epilogue (output projection) ----
#pragma unroll
        for (int mt = 0; mt < 4; ++mt) {
            int r0 = m0 + wm * 64 + mt * 16 + gid;
#pragma unroll
            for (int nt = 0; nt < 4; ++nt) {
                int col = n0 + wn * 32 + nt * 8 + 2 * tig;
                *(float2*)(C + (size_t)r0 * Ntot + col) = make_float2(c[mt][nt][0], c[mt][nt][1]);
                *(float2*)(C + (size_t)(r0 + 8) * Ntot + col) = make_float2(c[mt][nt][2], c[mt][nt][3]);
            }
        }
    } else {
        // ---- fused RoPE + scatter epilogue (QKV GEMM) ----
        const int region = n0 >> 11;            // 0=Q, 1=K, 2=V
        const int h = (n0 & 2047) >> 7;         // head
        const float sc = 0.08838834764831845f;  // 1/sqrt(128)
#pragma unroll
        for (int mt = 0; mt < 4; ++mt) {
            int r0 = m0 + wm * 64 + mt * 16 + gid;
#pragma unroll
            for (int half_row = 0; half_row < 2; ++half_row) {
                int row = r0 + half_row * 8;
                int s = row & 2047, b = row >> 11;
                size_t bo = ((size_t)(b * H_ + h) * S_ + s) * (size_t)D_;
#pragma unroll
                for (int nt = 0; nt < 4; ++nt) {
                    float v0 = c[mt][nt][half_row * 2 + 0];
                    float v1 = c[mt][nt][half_row * 2 + 1];
                    int i = wn * 16 + nt * 4 + tig;   // rotary pair index 0..63
                    if (region < 2) {
                        float co = fc[s * 128 + 2 * i];
                        float sn = fc[s * 128 + 2 * i + 1];
                        float re = v0 * co - v1 * sn;
                        float im = v1 * co + v0 * sn;
                        if (region == 0) { re *= sc; im *= sc; }
                        int p = i & 7;
                        int np = ((p & 3) << 1) | ((p >> 2) & 1);
                        int pos = (i >> 3) * 16 + np * 2;
                        __half2 hv = __floats2half2_rn(re, im);
                        if (region == 0) *(__half2*)(Qo + bo + pos) = hv;
                        else             *(__half2*)(Ko + bo + pos) = hv;
                    } else {
                        *(__half2*)(Vo + bo + 2 * i) = __floats2half2_rn(v0, v1);
                    }
                }
            }
        }
    }
}

// ============================================================================
// prep: fp32 -> fp16 with K-pair-interleave (one 16-elem block per thread)
// ============================================================================
__global__ __launch_bounds__(256) void round_copy_h(const float* __restrict__ in,
                                                    __half* __restrict__ out) {
    int i = blockIdx.x * 256 + threadIdx.x;
    const float* p = in + 16 * i;
    __half2 h[8];
#pragma unroll
    for (int j = 0; j < 8; ++j) {
        int pp = (j >> 1) | ((j & 1) << 2);   // inverse of np
        h[j] = __floats2half2_rn(p[2 * pp], p[2 * pp + 1]);
    }
    uint4* q = (uint4*)(out + 16 * i);
    q[0] = *(uint4*)(h);
    q[1] = *(uint4*)(h + 4);
}

// W[K][N] -> Wt[N][K] fp16, K-pair-interleaved
__global__ __launch_bounds__(256) void transpose_round_h(
    const float* __restrict__ W, __half* __restrict__ Wt, int K, int N)
{
    __shared__ float t[32][33];
    int n0 = blockIdx.x * 32, k0 = blockIdx.y * 32;
    int tx = threadIdx.x & 31, ty = threadIdx.x >> 5;
#pragma unroll
    for (int j = 0; j < 4; ++j)
        t[ty + j * 8][tx] = W[(size_t)(k0 + ty + j * 8) * N + n0 + tx];
    __syncthreads();
    int ktx = ilv16(tx);
#pragma unroll
    for (int j = 0; j < 4; ++j)
        Wt[(size_t)(n0 + ty + j * 8) * K + k0 + ktx] = __float2half(t[tx][ty + j * 8]);
}

// ============================================================================
// Flash attention fp16 mma (validated R9). BM=128, BN=64, 8 warps.
// ============================================================================
#define KSP 136
#define VSP 72
#define PSP 72
#define KS_H (64 * KSP)
#define VTS_H (128 * VSP)
#define PS_H (128 * PSP)
#define FL_SMEM ((2 * KS_H + 2 * VTS_H + PS_H) * 2)

__global__ __launch_bounds__(256, 1) void flash_mma(
    const __half* __restrict__ Qg, const __half* __restrict__ Kg,
    const __half* __restrict__ Vg, __half* __restrict__ Og)
{
    extern __shared__ __half smh[];
    __half* Ks  = smh;                 // [2][64][KSP]
    __half* Vts = smh + 2 * KS_H;      // [2][128][VSP]
    __half* Ps  = Vts + 2 * VTS_H;     // [128][PSP]

    const int tid  = threadIdx.x;
    const int wid  = tid >> 5;
    const int lane = tid & 31;
    const int gid  = lane >> 2;
    const int tig  = lane & 3;
    const int b = blockIdx.z, h = blockIdx.y;
    const int qt = (int)gridDim.x - 1 - (int)blockIdx.x;
    const int q0 = qt * 128;
    const int wrow = wid * 16;
    const size_t base = (size_t)(b * H_ + h) * S_ * D_;

    uint2 aq[8][2];
    {
        const __half* Qp0 = Qg + base + (size_t)(q0 + wrow + gid) * D_ + tig * 4;
        const __half* Qp1 = Qp0 + 8 * D_;
#pragma unroll
        for (int ks = 0; ks < 8; ++ks) {
            aq[ks][0] = *(const uint2*)(Qp0 + ks * 16);
            aq[ks][1] = *(const uint2*)(Qp1 + ks * 16);
        }
    }

    float accO[16][4];
#pragma unroll
    for (int nt = 0; nt < 16; ++nt)
#pragma unroll
        for (int t = 0; t < 4; ++t) accO[nt][t] = 0.f;
    float mrow[2] = {-3.0e38f, -3.0e38f};
    float lrow[2] = {0.f, 0.f};

    auto load_K = [&](int kt, int bf) {
        const __half* Kgp = Kg + base + (size_t)kt * 64 * D_;
        __half* dst = Ks + bf * KS_H;
#pragma unroll
        for (int j = 0; j < 4; ++j) {
            int q = tid + j * 256;
            int r = q >> 4, cc = q & 15;
            CP_ASYNC16(smem_u32(dst + r * KSP + cc * 8), Kgp + (size_t)r * D_ + cc * 8);
        }
    };
    auto load_V = [&](int kt, int bf) {
        const __half* Vgp = Vg + base + (size_t)kt * 64 * D_;
        __half* dst = Vts + bf * VTS_H;
#pragma unroll
        for (int j = 0; j < 8; ++j) {
            int e = tid + j * 256;
            int key = e & 63, d4 = e >> 6;
            uint2 v4 = *(const uint2*)(Vgp + (size_t)key * D_ + d4 * 4);
            __half2 lo = *(__half2*)&v4.x;
            __half2 hi = *(__half2*)&v4.y;
            int ik = ilv16(key);
            dst[(d4 * 4 + 0) * VSP + ik] = __low2half(lo);
            dst[(d4 * 4 + 1) * VSP + ik] = __high2half(lo);
            dst[(d4 * 4 + 2) * VSP + ik] = __low2half(hi);
            dst[(d4 * 4 + 3) * VSP + ik] = __high2half(hi);
        }
    };

    const int nkt = 2 * qt + 1;
    load_K(0, 0); CP_COMMIT();
    load_V(0, 0);

    const int row0s = (wrow + gid) * PSP;
    const int row1s = row0s + 8 * PSP;

    for (int kt = 0; kt <= nkt; ++kt) {
        const int cur = kt & 1, nxt = cur ^ 1;
        if (kt < nkt) { load_K(kt + 1, nxt); CP_COMMIT(); CP_WAIT1(); }
        else         { CP_WAIT0(); }
        __syncthreads();

        float sacc[8][4];
#pragma unroll
        for (int nt = 0; nt < 8; ++nt)
#pragma unroll
            for (int t = 0; t < 4; ++t) sacc[nt][t] = 0.f;

        const __half* Kb = Ks + cur * KS_H + gid * KSP + tig * 4;
#pragma unroll
        for (int ks = 0; ks < 8; ++ks) {
#pragma unroll
            for (int nt = 0; nt < 8; ++nt) {
                uint2 bb = *(const uint2*)(Kb + nt * 8 * KSP + ks * 16);
                mma_f16_16n8k16(sacc[nt][0], sacc[nt][1], sacc[nt][2], sacc[nt][3],
                                aq[ks][0].x, aq[ks][1].x, aq[ks][0].y, aq[ks][1].y,
                                bb.x, bb.y);
            }
        }

        if (kt < nkt) load_V(kt + 1, nxt);

        const int k0 = kt * 64;
        if (k0 + 63 > q0 + wrow) {
            int r0 = q0 + wrow + gid, r1 = r0 + 8;
#pragma unroll
            for (int nt = 0; nt < 8; ++nt) {
                int cA = k0 + nt * 8 + 2 * tig, cB = cA + 1;
                if (cA > r0) sacc[nt][0] = -1.0e30f;
                if (cB > r0) sacc[nt][1] = -1.0e30f;
                if (cA > r1) sacc[nt][2] = -1.0e30f;
                if (cB > r1) sacc[nt][3] = -1.0e30f;
            }
        }

        float mx0 = -3.0e38f, mx1 = -3.0e38f;
#pragma unroll
        for (int nt = 0; nt < 8; ++nt) {
            mx0 = fmaxf(mx0, fmaxf(sacc[nt][0], sacc[nt][1]));
            mx1 = fmaxf(mx1, fmaxf(sacc[nt][2], sacc[nt][3]));
        }
        mx0 = fmaxf(mx0, __shfl_xor_sync(0xffffffffu, mx0, 1));
        mx0 = fmaxf(mx0, __shfl_xor_sync(0xffffffffu, mx0, 2));
        mx1 = fmaxf(mx1, __shfl_xor_sync(0xffffffffu, mx1, 1));
        mx1 = fmaxf(mx1, __shfl_xor_sync(0xffffffffu, mx1, 2));

        float mn0 = fmaxf(mrow[0], mx0);
        float mn1 = fmaxf(mrow[1], mx1);
        float al0 = __expf(mrow[0] - mn0);
        float al1 = __expf(mrow[1] - mn1);
        mrow[0] = mn0; mrow[1] = mn1;

        float s0 = 0.f, s1 = 0.f;
#pragma unroll
        for (int nt = 0; nt < 8; ++nt) {
            sacc[nt][0] = __expf(sacc[nt][0] - mn0);
            sacc[nt][1] = __expf(sacc[nt][1] - mn0);
            sacc[nt][2] = __expf(sacc[nt][2] - mn1);
            sacc[nt][3] = __expf(sacc[nt][3] - mn1);
            s0 += sacc[nt][0] + sacc[nt][1];
            s1 += sacc[nt][2] + sacc[nt][3];
        }
        s0 += __shfl_xor_sync(0xffffffffu, s0, 1);
        s0 += __shfl_xor_sync(0xffffffffu, s0, 2);
        s1 += __shfl_xor_sync(0xffffffffu, s1, 1);
        s1 += __shfl_xor_sync(0xffffffffu, s1, 2);
        lrow[0] = lrow[0] * al0 + s0;
        lrow[1] = lrow[1] * al1 + s1;

#pragma unroll
        for (int nt = 0; nt < 16; ++nt) {
            accO[nt][0] *= al0; accO[nt][1] *= al0;
            accO[nt][2] *= al1; accO[nt][3] *= al1;
        }
#pragma unroll
        for (int nt = 0; nt < 8; ++nt) {
            int np = 2 * tig + (nt & 1);
            int off = (nt >> 1) * 16 + np * 2;
            *(__half2*)(Ps + row0s + off) = __floats2half2_rn(sacc[nt][0], sacc[nt][1]);
            *(__half2*)(Ps + row1s + off) = __floats2half2_rn(sacc[nt][2], sacc[nt][3]);
        }
        __syncthreads();

        const __half* Vb = Vts + cur * VTS_H + gid * VSP + tig * 4;
        const __half* Pb0 = Ps + row0s + tig * 4;
        const __half* Pb1 = Ps + row1s + tig * 4;
#pragma unroll
        for (int ks2 = 0; ks2 < 4; ++ks2) {
            uint2 pa0 = *(const uint2*)(Pb0 + ks2 * 16);
            uint2 pa1 = *(const uint2*)(Pb1 + ks2 * 16);
#pragma unroll
            for (int nt = 0; nt < 16; ++nt) {
                uint2 vb = *(const uint2*)(Vb + nt * 8 * VSP + ks2 * 16);
                mma_f16_16n8k16(accO[nt][0], accO[nt][1], accO[nt][2], accO[nt][3],
                                pa0.x, pa1.x, pa0.y, pa1.y,
                                vb.x, vb.y);
            }
        }
    }

    float inv0 = 1.f / lrow[0];
    float inv1 = 1.f / lrow[1];
    int qrow = q0 + wrow + gid;
    __half* O0 = Og + (size_t)(b * S_ + qrow) * E_ + h * D_;
    __half* O1 = O0 + 8 * (size_t)E_;
#pragma unroll
    for (int nt = 0; nt < 16; ++nt) {
        int np = 2 * tig + (nt & 1);
        int off = (nt >> 1) * 16 + np * 2;
        *(__half2*)(O0 + off) = __floats2half2_rn(accO[nt][0] * inv0, accO[nt][1] * inv0);
        *(__half2*)(O1 + off) = __floats2half2_rn(accO[nt][2] * inv1, accO[nt][3] * inv1);
    }
}

// ============================================================================
// kernel_launch
// ============================================================================
extern "C" void kernel_launch(void* const* d_in, const int* in_sizes, int n_in,
                              void* d_out, int out_size)
{
    const float* x    = (const float*)d_in[0];
    const float* Wqkv = (const float*)d_in[1];
    const float* Wo   = (const float*)d_in[2];
    const float* fc   = (const float*)d_in[3];
    float* out = (float*)d_out;

    __half *xh, *wqkvT, *woT, *Q, *K, *V, *AO;
    cudaGetSymbolAddress((void**)&xh, g_xh);
    cudaGetSymbolAddress((void**)&wqkvT, g_wqkvT);
    cudaGetSymbolAddress((void**)&woT, g_woT);
    cudaGetSymbolAddress((void**)&Q, g_qh);
    cudaGetSymbolAddress((void**)&K, g_kh);
    cudaGetSymbolAddress((void**)&V, g_vh);
    cudaGetSymbolAddress((void**)&AO, g_aoh);

    cudaFuncSetAttribute(gemm_mma, cudaFuncAttributeMaxDynamicSharedMemorySize, GEMM_SMEM);
    cudaFuncSetAttribute(flash_mma, cudaFuncAttributeMaxDynamicSharedMemorySize, FL_SMEM);

    round_copy_h<<<(B_ * S_ * E_) / 16 / 256, 256>>>(x, xh);
    {
        dim3 g(E3_ / 32, E_ / 32);
        transpose_round_h<<<g, 256>>>(Wqkv, wqkvT, E_, E3_);
    }
    {
        dim3 g(E_ / 32, E_ / 32);
        transpose_round_h<<<g, 256>>>(Wo, woT, E_, E_);
    }

    // 1) QKV GEMM with fused RoPE+scatter epilogue
    {
        dim3 grid(E3_ / 128, (B_ * S_) / 128);
        gemm_mma<<<grid, 256, GEMM_SMEM>>>(xh, wqkvT, nullptr, fc, Q, K, V,
                                           B_ * S_, E3_, E_, 1);
    }
    // 2) flash attention
    {
        dim3 grid(S_ / 128, H_, B_);
        flash_mma<<<grid, 256, FL_SMEM>>>(Q, K, V, AO);
    }
    // 3) out = AO @ woT^T (plain fp32 epilogue)
    {
        dim3 grid(E_ / 128, (B_ * S_) / 128);
        gemm_mma<<<grid, 256, GEMM_SMEM>>>(AO, woT, out, nullptr, nullptr, nullptr,
                                           nullptr, B_ * S_, E_, E_, 0);
    }
}